// round 8
// baseline (speedup 1.0000x reference)
#include <cuda_runtime.h>
#include <cuda_bf16.h>
#include <cstdint>

#define HID   256
#define NN    4096
#define BATCH 4
#define ROWS  (BATCH*NN)   // 16384
#define KNN   8
#define NCAND 16
#define NTILE 32           // 4096/128 col tiles
#define PERT  10           // per-(row,tile) candidates kept

// ---- scratch (static device globals; no runtime allocation) ----
__device__ __nv_bfloat16 d_Qh[(size_t)ROWS * HID];
__device__ __nv_bfloat16 d_Kh[(size_t)ROWS * HID];
__device__ float d_Qf[(size_t)ROWS * HID];
__device__ float d_Kf[(size_t)ROWS * HID];
__device__ unsigned long long d_T10[(size_t)ROWS * NTILE * PERT];  // 40 MB
__device__ float d_PM[(size_t)ROWS * NTILE];
__device__ float d_PZ[(size_t)ROWS * NTILE];
__device__ int   d_C16[ROWS * NCAND];
__device__ float d_Mv[ROWS];
__device__ float d_Zv[ROWS];
__device__ float d_TopV[ROWS * KNN];
__device__ int   d_TopI[ROWS * KNN];

typedef unsigned long long u64;

// ============================================================================
// PTX helpers (all sm_80-baseline)
// ============================================================================
__device__ __forceinline__ uint32_t smem_u32(const void* p) {
    uint32_t a;
    asm("{ .reg .u64 t; cvta.to.shared.u64 t, %1; cvt.u32.u64 %0, t; }" : "=r"(a) : "l"(p));
    return a;
}
__device__ __forceinline__ void cp16(uint32_t dst, const void* src) {
    asm volatile("cp.async.cg.shared.global [%0], [%1], 16;" :: "r"(dst), "l"(src));
}
__device__ __forceinline__ void ldsm4(uint32_t r[4], uint32_t addr) {
    asm volatile("ldmatrix.sync.aligned.m8n8.x4.shared.b16 {%0,%1,%2,%3}, [%4];"
                 : "=r"(r[0]), "=r"(r[1]), "=r"(r[2]), "=r"(r[3]) : "r"(addr));
}
__device__ __forceinline__ void mma_bf16(float c[4], const uint32_t a[4],
                                         uint32_t b0, uint32_t b1) {
    asm volatile(
        "mma.sync.aligned.m16n8k16.row.col.f32.bf16.bf16.f32 "
        "{%0,%1,%2,%3}, {%4,%5,%6,%7}, {%8,%9}, {%0,%1,%2,%3};"
        : "+f"(c[0]), "+f"(c[1]), "+f"(c[2]), "+f"(c[3])
        : "r"(a[0]), "r"(a[1]), "r"(a[2]), "r"(a[3]), "r"(b0), "r"(b1));
}
__device__ __forceinline__ u64 pk2(float lo, float hi) {
    u64 r;
    asm("mov.b64 %0, {%1, %2};" : "=l"(r) : "f"(lo), "f"(hi));
    return r;
}
__device__ __forceinline__ void upk2(u64 v, float& lo, float& hi) {
    asm("mov.b64 {%0, %1}, %2;" : "=f"(lo), "=f"(hi) : "l"(v));
}
__device__ __forceinline__ void fma2(u64& d, u64 a, u64 b) {
    asm("fma.rn.f32x2 %0, %1, %2, %0;" : "+l"(d) : "l"(a), "l"(b));
}
__device__ __forceinline__ uint32_t mono_f(float f) {
    uint32_t u = __float_as_uint(f);
    return (u & 0x80000000u) ? ~u : (u | 0x80000000u);
}
__device__ __forceinline__ float unmono_f(uint32_t m) {
    uint32_t u = (m & 0x80000000u) ? (m ^ 0x80000000u) : ~m;
    return __uint_as_float(u);
}

// ============================================================================
// Projection: O = x @ W^T + b -> fp32 copy + bf16 (hi only).  (R7-proven)
// ============================================================================
#define BM 128
#define BN 128
#define BK 16
#define TM 8
#define TN 8

__global__ __launch_bounds__(256, 2) void proj_kernel(
    const float* __restrict__ A, const float* __restrict__ B,
    const float* __restrict__ bias,
    float* __restrict__ Of, __nv_bfloat16* __restrict__ Oh)
{
    const int Kd = HID;
    const int tid = threadIdx.x;
    const int tx  = tid & 15;
    const int ty  = tid >> 4;
    const long bm = (long)blockIdx.y * BM;
    const long bn = (long)blockIdx.x * BN;

    __shared__ float As[2][BK][BM];
    __shared__ float Bs[2][BK][BN];

    u64 acc[TM][TN/2];
#pragma unroll
    for (int i = 0; i < TM; i++)
#pragma unroll
        for (int j = 0; j < TN/2; j++) acc[i][j] = 0ULL;

    const int lr = tid >> 1;
    const int lc = (tid & 1) * 8;
    const float* Abase = A + (bm + lr) * Kd + lc;
    const float* Bbase = B + (bn + lr) * Kd + lc;

    float4 ra0, ra1, rb0, rb1;
    ra0 = *(const float4*)(Abase);
    ra1 = *(const float4*)(Abase + 4);
    rb0 = *(const float4*)(Bbase);
    rb1 = *(const float4*)(Bbase + 4);
    {
        As[0][lc+0][lr]=ra0.x; As[0][lc+1][lr]=ra0.y; As[0][lc+2][lr]=ra0.z; As[0][lc+3][lr]=ra0.w;
        As[0][lc+4][lr]=ra1.x; As[0][lc+5][lr]=ra1.y; As[0][lc+6][lr]=ra1.z; As[0][lc+7][lr]=ra1.w;
        Bs[0][lc+0][lr]=rb0.x; Bs[0][lc+1][lr]=rb0.y; Bs[0][lc+2][lr]=rb0.z; Bs[0][lc+3][lr]=rb0.w;
        Bs[0][lc+4][lr]=rb1.x; Bs[0][lc+5][lr]=rb1.y; Bs[0][lc+6][lr]=rb1.z; Bs[0][lc+7][lr]=rb1.w;
    }
    __syncthreads();

    const int KT = Kd / BK;
    for (int kt = 0; kt < KT; ++kt) {
        const int buf = kt & 1;
        if (kt + 1 < KT) {
            const float* Ap = Abase + (kt + 1) * BK;
            const float* Bp = Bbase + (kt + 1) * BK;
            ra0 = *(const float4*)(Ap);  ra1 = *(const float4*)(Ap + 4);
            rb0 = *(const float4*)(Bp);  rb1 = *(const float4*)(Bp + 4);
        }
#pragma unroll
        for (int kk = 0; kk < BK; kk++) {
            float4 a0 = *(const float4*)&As[buf][kk][ty * TM];
            float4 a1 = *(const float4*)&As[buf][kk][ty * TM + 4];
            ulonglong2 b0 = *(const ulonglong2*)&Bs[buf][kk][tx * TN];
            ulonglong2 b1 = *(const ulonglong2*)&Bs[buf][kk][tx * TN + 4];
            u64 ad[TM] = {
                pk2(a0.x,a0.x), pk2(a0.y,a0.y), pk2(a0.z,a0.z), pk2(a0.w,a0.w),
                pk2(a1.x,a1.x), pk2(a1.y,a1.y), pk2(a1.z,a1.z), pk2(a1.w,a1.w)
            };
            u64 bd[4] = { b0.x, b0.y, b1.x, b1.y };
#pragma unroll
            for (int i = 0; i < TM; i++) {
                fma2(acc[i][0], ad[i], bd[0]);
                fma2(acc[i][1], ad[i], bd[1]);
                fma2(acc[i][2], ad[i], bd[2]);
                fma2(acc[i][3], ad[i], bd[3]);
            }
        }
        if (kt + 1 < KT) {
            const int nb = buf ^ 1;
            As[nb][lc+0][lr]=ra0.x; As[nb][lc+1][lr]=ra0.y; As[nb][lc+2][lr]=ra0.z; As[nb][lc+3][lr]=ra0.w;
            As[nb][lc+4][lr]=ra1.x; As[nb][lc+5][lr]=ra1.y; As[nb][lc+6][lr]=ra1.z; As[nb][lc+7][lr]=ra1.w;
            Bs[nb][lc+0][lr]=rb0.x; Bs[nb][lc+1][lr]=rb0.y; Bs[nb][lc+2][lr]=rb0.z; Bs[nb][lc+3][lr]=rb0.w;
            Bs[nb][lc+4][lr]=rb1.x; Bs[nb][lc+5][lr]=rb1.y; Bs[nb][lc+6][lr]=rb1.z; Bs[nb][lc+7][lr]=rb1.w;
        }
        __syncthreads();
    }

#pragma unroll
    for (int i = 0; i < TM; i++) {
        const long rrow = bm + ty * TM + i;
        const long cb = bn + tx * TN;
        float o[8];
        upk2(acc[i][0], o[0], o[1]);
        upk2(acc[i][1], o[2], o[3]);
        upk2(acc[i][2], o[4], o[5]);
        upk2(acc[i][3], o[6], o[7]);
        const float* bp = bias + cb;
#pragma unroll
        for (int j = 0; j < 8; j++) {
            float v = o[j] + bp[j];
            o[j] = v;
            Oh[rrow * HID + cb + j] = __float2bfloat16(v);
        }
        *(float4*)(Of + rrow * HID + cb)     = make_float4(o[0], o[1], o[2], o[3]);
        *(float4*)(Of + rrow * HID + cb + 4) = make_float4(o[4], o[5], o[6], o[7]);
    }
}

// ============================================================================
// Scores: bf16 mma.sync mainloop (3-stage cp.async) + FUSED per-row-tile
// reduction epilogue (top-10 keys + partial max/sumexp). No global S matrix.
// Dynamic smem layout:
//   mainloop: sA 3 stages @ [0, 30720), sB @ [30720, 61440)
//   epilogue: fp32 tile 128x129 @ [0, 66048), lists @ 66048 (128*10 u64),
//             pm @ 76288 (128 f32), pz @ 76800 (128 f32)   total 77312
// ============================================================================
#define SPITCH 40
#define SC_STG  10240                 // one stage of one matrix (128*40*2)
#define SC_SMEM 77312

__global__ __launch_bounds__(256) void scores_kernel()
{
    extern __shared__ __align__(16) char smem[];

    const int tid = threadIdx.x;
    const int wid = tid >> 5, l = tid & 31;
    const int wm = wid & 1;
    const int wn = wid >> 1;
    const long b  = blockIdx.z;
    const long bm = (long)blockIdx.y * 128;
    const long bn = (long)blockIdx.x * 128;

    const uint32_t sAu = smem_u32(smem);
    const uint32_t sBu = sAu + 3 * SC_STG;

    float cacc[4][4][4];
#pragma unroll
    for (int mi = 0; mi < 4; mi++)
#pragma unroll
        for (int ni = 0; ni < 4; ni++)
#pragma unroll
            for (int e = 0; e < 4; e++) cacc[mi][ni][e] = 0.f;

    auto fill = [&](int stage, int c) {
        const int kb = c * 64;   // 32 bf16 per chunk
        const char* Ag = (const char*)(d_Qh + (b * NN + bm) * HID) + kb;
        const char* Bg = (const char*)(d_Kh + (b * NN + bn) * HID) + kb;
        const uint32_t da = sAu + stage * SC_STG;
        const uint32_t db = sBu + stage * SC_STG;
#pragma unroll
        for (int i = 0; i < 2; i++) {
            const int idx = tid + i * 256;
            const int row = idx >> 2, ch = idx & 3;
            cp16(da + row * (SPITCH * 2) + ch * 16, Ag + (size_t)row * (HID * 2) + ch * 16);
            cp16(db + row * (SPITCH * 2) + ch * 16, Bg + (size_t)row * (HID * 2) + ch * 16);
        }
    };

    fill(0, 0);
    asm volatile("cp.async.commit_group;" ::: "memory");
    fill(1, 1);
    asm volatile("cp.async.commit_group;" ::: "memory");

    const int rA = ((l >> 3) & 1) * 8 + (l & 7);
    const int cA = (l >> 4) * 16;
    const int rB = (l >> 4) * 8 + (l & 7);
    const int cB = ((l >> 3) & 1) * 16;

    for (int c = 0; c < 8; c++) {
        const int s = c % 3;
        if (c < 7) asm volatile("cp.async.wait_group 1;" ::: "memory");
        else       asm volatile("cp.async.wait_group 0;" ::: "memory");
        __syncthreads();

        const uint32_t ab = sAu + s * SC_STG;
        const uint32_t bb = sBu + s * SC_STG;

        uint32_t af[2][4][4];
        uint32_t bf[2][2][4];
#pragma unroll
        for (int kk = 0; kk < 2; kk++) {
#pragma unroll
            for (int mi = 0; mi < 4; mi++)
                ldsm4(af[kk][mi],
                      ab + (uint32_t)(wm * 64 + mi * 16 + rA) * (SPITCH * 2) + kk * 32 + cA);
#pragma unroll
            for (int bi = 0; bi < 2; bi++)
                ldsm4(bf[kk][bi],
                      bb + (uint32_t)(wn * 32 + bi * 16 + rB) * (SPITCH * 2) + kk * 32 + cB);
        }

        if (c + 2 < 8) {
            fill((c + 2) % 3, c + 2);
            asm volatile("cp.async.commit_group;" ::: "memory");
        }

#pragma unroll
        for (int kk = 0; kk < 2; kk++)
#pragma unroll
            for (int mi = 0; mi < 4; mi++)
#pragma unroll
                for (int ni = 0; ni < 4; ni++) {
                    const int bi = ni >> 1, p = ni & 1;
                    mma_bf16(cacc[mi][ni], af[kk][mi],
                             bf[kk][bi][p * 2], bf[kk][bi][p * 2 + 1]);
                }
    }

    // ===== fused epilogue: per-row-tile top-10 + partial (m, z) =====
    float* tileS = (float*)smem;
    u64*   lists = (u64*)(smem + 66048);
    float* pmh   = (float*)(smem + 76288);
    float* pzh   = (float*)(smem + 76800);

    __syncthreads();   // all mainloop smem reads complete before overwrite

    {
        const int g2 = l >> 2, tg2 = l & 3;
#pragma unroll
        for (int mi = 0; mi < 4; mi++) {
            const int r0 = wm * 64 + mi * 16 + g2;
#pragma unroll
            for (int ni = 0; ni < 4; ni++) {
                const int c0 = wn * 32 + ni * 8 + tg2 * 2;
                tileS[r0 * 129 + c0]         = cacc[mi][ni][0] * 0.0625f;
                tileS[r0 * 129 + c0 + 1]     = cacc[mi][ni][1] * 0.0625f;
                tileS[(r0 + 8) * 129 + c0]   = cacc[mi][ni][2] * 0.0625f;
                tileS[(r0 + 8) * 129 + c0+1] = cacc[mi][ni][3] * 0.0625f;
            }
        }
    }
    __syncthreads();

    const int rr = tid & 127;          // local row
    const int hh = tid >> 7;           // half (cols 0..63 / 64..127)
    const float* rowp = tileS + rr * 129 + hh * 64;
    const int gcolBase = (int)bn + hh * 64;

    u64 a[PERT];
    const u64 KINIT = ((u64)mono_f(-3.0e38f) << 32);
#pragma unroll
    for (int k = 0; k < PERT; k++) a[k] = KINIT;
    float thr = -3.0e38f, m = -3.0e38f;

    for (int j = 0; j < 64; j++) {
        const float val = rowp[j];
        m = fmaxf(m, val);
        if (val >= thr) {
            const u64 key = ((u64)mono_f(val) << 32)
                          | (unsigned)(4095 - (gcolBase + j));
            if (key > a[PERT-1]) {
                a[PERT-1] = key;
#pragma unroll
                for (int t = PERT-1; t > 0; t--)
                    if (a[t] > a[t-1]) { u64 tmp = a[t]; a[t] = a[t-1]; a[t-1] = tmp; }
                thr = unmono_f((uint32_t)(a[PERT-1] >> 32));
            }
        }
    }
    float z = 0.f;
    for (int j = 0; j < 64; j++) z += __expf(rowp[j] - m);

    if (hh) {
#pragma unroll
        for (int k = 0; k < PERT; k++) lists[rr * PERT + k] = a[k];
        pmh[rr] = m;
        pzh[rr] = z;
    }
    __syncthreads();

    if (!hh) {
        const u64* Bl = lists + rr * PERT;
        u64 out[PERT];
        int i = 0, jj = 0;
#pragma unroll
        for (int k = 0; k < PERT; k++) {
            const u64 x = (i  < PERT) ? a[i]   : 0ULL;
            const u64 y = (jj < PERT) ? Bl[jj] : 0ULL;
            if (x >= y) { out[k] = x; i++; } else { out[k] = y; jj++; }
        }
        const float m2 = pmh[rr], z2 = pzh[rr];
        const float M  = fmaxf(m, m2);
        const float Zc = z * __expf(m - M) + z2 * __expf(m2 - M);

        const size_t base = ((size_t)(b * NN + bm + rr)) * NTILE + blockIdx.x;
        u64* dst = d_T10 + base * PERT;
#pragma unroll
        for (int k = 0; k < PERT; k++) dst[k] = out[k];
        d_PM[base] = M;
        d_PZ[base] = Zc;
    }
}

// ============================================================================
// merge: one warp per row — tournament over 32 sorted-10 tile lists -> top-16,
// plus exact max-of-maxes m and rescaled Z.
// ============================================================================
__global__ __launch_bounds__(256) void merge_kernel()
{
    const int row  = blockIdx.x * 8 + (threadIdx.x >> 5);
    const int lane = threadIdx.x & 31;
    const size_t base = (size_t)row * NTILE + lane;

    u64 h[PERT];
    const u64* src = d_T10 + base * PERT;
#pragma unroll
    for (int k = 0; k < PERT; k++) h[k] = src[k];
    const float pm = d_PM[base];
    const float pz = d_PZ[base];

    const uint32_t mk = __reduce_max_sync(0xFFFFFFFFu, mono_f(pm));
    const float m = unmono_f(mk);
    float z = pz * __expf(pm - m);
#pragma unroll
    for (int o = 16; o; o >>= 1) z += __shfl_xor_sync(0xFFFFFFFFu, z, o);

    int head = 0;
    u64 cur = h[0];
    for (int r = 0; r < NCAND; r++) {
        const uint32_t hi  = (uint32_t)(cur >> 32);
        const uint32_t win = __reduce_max_sync(0xFFFFFFFFu, hi);
        const uint32_t bal = __ballot_sync(0xFFFFFFFFu, hi == win);
        const int wl = __ffs(bal) - 1;
        if (lane == wl) {
            d_C16[row * NCAND + r] = 4095 - (int)(cur & 0xFFFFFFFFu);
            head++;
            cur = (head < PERT) ? h[head] : 0ULL;
        }
    }
    if (lane == 0) { d_Mv[row] = m; d_Zv[row] = z; }
}

// ============================================================================
// rescore: fp32 SEQUENTIAL-k fma chain (R1/ref-matched). (R6/R7-proven)
// ============================================================================
__global__ __launch_bounds__(256) void rescore_kernel()
{
    __shared__ float sq[8][HID];
    const int wid = threadIdx.x >> 5, lane = threadIdx.x & 31;
    const int row = blockIdx.x * 8 + wid;
    const int b = row >> 12;

    for (int i = lane; i < HID; i += 32)
        sq[wid][i] = d_Qf[(size_t)row * HID + i];
    __syncwarp();

    float s = 0.f; int j = 0;
    if (lane < NCAND) {
        j = d_C16[row * NCAND + lane];
        const float* kr = d_Kf + ((size_t)((b << 12) + j)) * HID;
        float acc = 0.f;
#pragma unroll
        for (int k = 0; k < HID; k++)
            acc = fmaf(sq[wid][k], __ldg(kr + k), acc);
        s = acc * 0.0625f;
    }

    float scs[NCAND]; int ixs[NCAND];
#pragma unroll
    for (int c = 0; c < NCAND; c++) {
        scs[c] = __shfl_sync(0xFFFFFFFFu, s, c);
        ixs[c] = __shfl_sync(0xFFFFFFFFu, j, c);
    }

    if (lane == 0) {
        u64 key[NCAND];
#pragma unroll
        for (int c = 0; c < NCAND; c++)
            key[c] = ((u64)mono_f(scs[c]) << 32) | (unsigned)(4095 - ixs[c]);
        for (int i = 1; i < NCAND; i++) {
            u64 kv = key[i];
            int jj = i;
            while (jj > 0 && key[jj-1] < kv) { key[jj] = key[jj-1]; jj--; }
            key[jj] = kv;
        }
        const float m = d_Mv[row], z = d_Zv[row];
        float ev[KNN]; int oi[KNN]; float E8 = 0.f;
#pragma unroll
        for (int k = 0; k < KNN; k++) {
            const uint32_t mv = (uint32_t)(key[k] >> 32);
            const uint32_t u = (mv & 0x80000000u) ? (mv ^ 0x80000000u) : ~mv;
            const float sv = __uint_as_float(u);
            oi[k] = 4095 - (int)(key[k] & 0xFFFFFFFFu);
            ev[k] = __expf(sv - m);
            E8 += ev[k];
        }
        const float inv = 1.0f / (E8 + 1e-6f * z);
#pragma unroll
        for (int k = 0; k < KNN; k++) {
            d_TopV[row * KNN + k] = ev[k] * inv;
            d_TopI[row * KNN + k] = oi[k];
        }
    }
}

// ============================================================================
// Output: zero then symmetric sparse scatter (0.5*(A + A^T))
// ============================================================================
__global__ void zero_kernel(float* __restrict__ out)
{
    const size_t i = (size_t)blockIdx.x * blockDim.x + threadIdx.x;
    ((float4*)out)[i] = make_float4(0.f, 0.f, 0.f, 0.f);
}

__global__ void scatter_kernel(float* __restrict__ out)
{
    const int t = blockIdx.x * blockDim.x + threadIdx.x;
    if (t >= ROWS * KNN) return;
    const int row = t / KNN;
    const int b = row >> 12;
    const int i = row & (NN - 1);
    const int j = d_TopI[t];
    const float v = 0.5f * d_TopV[t];
    float* base = out + (size_t)b * NN * NN;
    atomicAdd(base + (size_t)i * NN + j, v);
    atomicAdd(base + (size_t)j * NN + i, v);
}

// ============================================================================
extern "C" void kernel_launch(void* const* d_in, const int* in_sizes, int n_in,
                              void* d_out, int out_size)
{
    const float* x  = (const float*)d_in[0];
    const float* Wq = (const float*)d_in[1];
    const float* bq = (const float*)d_in[2];
    const float* Wk = (const float*)d_in[3];
    const float* bk = (const float*)d_in[4];
    float* out = (float*)d_out;

    void *pqh, *pkh, *pqf, *pkf;
    cudaGetSymbolAddress(&pqh, d_Qh);
    cudaGetSymbolAddress(&pkh, d_Kh);
    cudaGetSymbolAddress(&pqf, d_Qf);
    cudaGetSymbolAddress(&pkf, d_Kf);

    cudaFuncSetAttribute(scores_kernel,
                         cudaFuncAttributeMaxDynamicSharedMemorySize, SC_SMEM);

    // 1) projections -> fp32 + bf16
    dim3 gProj(HID / BN, ROWS / BM, 1);
    proj_kernel<<<gProj, 256>>>(x, Wq, bq, (float*)pqf, (__nv_bfloat16*)pqh);
    proj_kernel<<<gProj, 256>>>(x, Wk, bk, (float*)pkf, (__nv_bfloat16*)pkh);

    // 2) scores (bf16 mma) with fused per-row-tile selection epilogue
    dim3 gS(NN / 128, NN / 128, BATCH);
    scores_kernel<<<gS, 256, SC_SMEM>>>();

    // 3) per-row merge of 32 tile lists -> top-16 candidates + (m, Z)
    merge_kernel<<<ROWS / 8, 256>>>();

    // 4) fp32 sequential-k rescoring + exact top-8 pick
    rescore_kernel<<<ROWS / 8, 256>>>();

    // 5) zero output, 6) symmetric sparse scatter
    zero_kernel<<<((size_t)BATCH * NN * NN / 4) / 256, 256>>>(out);
    scatter_kernel<<<(ROWS * KNN + 255) / 256, 256>>>(out);
}

// round 9
// speedup vs baseline: 1.3243x; 1.3243x over previous
#include <cuda_runtime.h>
#include <cuda_bf16.h>
#include <cstdint>

#define HID   256
#define NN    4096
#define BATCH 4
#define ROWS  (BATCH*NN)   // 16384
#define KNN   8
#define NCAND 16

// ---- scratch (static device globals; no runtime allocation) ----
__device__ __nv_bfloat16 d_Qh[(size_t)ROWS * HID];
__device__ __nv_bfloat16 d_Kh[(size_t)ROWS * HID];
__device__ float d_Qf[(size_t)ROWS * HID];
__device__ float d_Kf[(size_t)ROWS * HID];
__device__ float d_Sg[(size_t)BATCH * NN * NN];         // 268 MB
__device__ int   d_C16[ROWS * NCAND];
__device__ float d_Mv[ROWS];
__device__ float d_Zv[ROWS];
__device__ float d_TopV[ROWS * KNN];
__device__ int   d_TopI[ROWS * KNN];

typedef unsigned long long u64;

// ============================================================================
// PTX helpers (all sm_80-baseline)
// ============================================================================
__device__ __forceinline__ uint32_t smem_u32(const void* p) {
    uint32_t a;
    asm("{ .reg .u64 t; cvta.to.shared.u64 t, %1; cvt.u32.u64 %0, t; }" : "=r"(a) : "l"(p));
    return a;
}
__device__ __forceinline__ void cp16(uint32_t dst, const void* src) {
    asm volatile("cp.async.cg.shared.global [%0], [%1], 16;" :: "r"(dst), "l"(src));
}
__device__ __forceinline__ void ldsm4(uint32_t r[4], uint32_t addr) {
    asm volatile("ldmatrix.sync.aligned.m8n8.x4.shared.b16 {%0,%1,%2,%3}, [%4];"
                 : "=r"(r[0]), "=r"(r[1]), "=r"(r[2]), "=r"(r[3]) : "r"(addr));
}
__device__ __forceinline__ void mma_bf16(float c[4], const uint32_t a[4],
                                         uint32_t b0, uint32_t b1) {
    asm volatile(
        "mma.sync.aligned.m16n8k16.row.col.f32.bf16.bf16.f32 "
        "{%0,%1,%2,%3}, {%4,%5,%6,%7}, {%8,%9}, {%0,%1,%2,%3};"
        : "+f"(c[0]), "+f"(c[1]), "+f"(c[2]), "+f"(c[3])
        : "r"(a[0]), "r"(a[1]), "r"(a[2]), "r"(a[3]), "r"(b0), "r"(b1));
}
__device__ __forceinline__ u64 pk2(float lo, float hi) {
    u64 r;
    asm("mov.b64 %0, {%1, %2};" : "=l"(r) : "f"(lo), "f"(hi));
    return r;
}
__device__ __forceinline__ void upk2(u64 v, float& lo, float& hi) {
    asm("mov.b64 {%0, %1}, %2;" : "=f"(lo), "=f"(hi) : "l"(v));
}
__device__ __forceinline__ void fma2(u64& d, u64 a, u64 b) {
    asm("fma.rn.f32x2 %0, %1, %2, %0;" : "+l"(d) : "l"(a), "l"(b));
}
__device__ __forceinline__ uint32_t mono_f(float f) {
    uint32_t u = __float_as_uint(f);
    return (u & 0x80000000u) ? ~u : (u | 0x80000000u);
}
__device__ __forceinline__ float unmono_f(uint32_t m) {
    uint32_t u = (m & 0x80000000u) ? (m ^ 0x80000000u) : ~m;
    return __uint_as_float(u);
}

// ============================================================================
// Projection: O = x @ W^T + b -> fp32 copy + bf16 (hi only).  (R7-proven)
// ============================================================================
#define BM 128
#define BN 128
#define BK 16
#define TM 8
#define TN 8

__global__ __launch_bounds__(256, 2) void proj_kernel(
    const float* __restrict__ A, const float* __restrict__ B,
    const float* __restrict__ bias,
    float* __restrict__ Of, __nv_bfloat16* __restrict__ Oh)
{
    const int Kd = HID;
    const int tid = threadIdx.x;
    const int tx  = tid & 15;
    const int ty  = tid >> 4;
    const long bm = (long)blockIdx.y * BM;
    const long bn = (long)blockIdx.x * BN;

    __shared__ float As[2][BK][BM];
    __shared__ float Bs[2][BK][BN];

    u64 acc[TM][TN/2];
#pragma unroll
    for (int i = 0; i < TM; i++)
#pragma unroll
        for (int j = 0; j < TN/2; j++) acc[i][j] = 0ULL;

    const int lr = tid >> 1;
    const int lc = (tid & 1) * 8;
    const float* Abase = A + (bm + lr) * Kd + lc;
    const float* Bbase = B + (bn + lr) * Kd + lc;

    float4 ra0, ra1, rb0, rb1;
    ra0 = *(const float4*)(Abase);
    ra1 = *(const float4*)(Abase + 4);
    rb0 = *(const float4*)(Bbase);
    rb1 = *(const float4*)(Bbase + 4);
    {
        As[0][lc+0][lr]=ra0.x; As[0][lc+1][lr]=ra0.y; As[0][lc+2][lr]=ra0.z; As[0][lc+3][lr]=ra0.w;
        As[0][lc+4][lr]=ra1.x; As[0][lc+5][lr]=ra1.y; As[0][lc+6][lr]=ra1.z; As[0][lc+7][lr]=ra1.w;
        Bs[0][lc+0][lr]=rb0.x; Bs[0][lc+1][lr]=rb0.y; Bs[0][lc+2][lr]=rb0.z; Bs[0][lc+3][lr]=rb0.w;
        Bs[0][lc+4][lr]=rb1.x; Bs[0][lc+5][lr]=rb1.y; Bs[0][lc+6][lr]=rb1.z; Bs[0][lc+7][lr]=rb1.w;
    }
    __syncthreads();

    const int KT = Kd / BK;
    for (int kt = 0; kt < KT; ++kt) {
        const int buf = kt & 1;
        if (kt + 1 < KT) {
            const float* Ap = Abase + (kt + 1) * BK;
            const float* Bp = Bbase + (kt + 1) * BK;
            ra0 = *(const float4*)(Ap);  ra1 = *(const float4*)(Ap + 4);
            rb0 = *(const float4*)(Bp);  rb1 = *(const float4*)(Bp + 4);
        }
#pragma unroll
        for (int kk = 0; kk < BK; kk++) {
            float4 a0 = *(const float4*)&As[buf][kk][ty * TM];
            float4 a1 = *(const float4*)&As[buf][kk][ty * TM + 4];
            ulonglong2 b0 = *(const ulonglong2*)&Bs[buf][kk][tx * TN];
            ulonglong2 b1 = *(const ulonglong2*)&Bs[buf][kk][tx * TN + 4];
            u64 ad[TM] = {
                pk2(a0.x,a0.x), pk2(a0.y,a0.y), pk2(a0.z,a0.z), pk2(a0.w,a0.w),
                pk2(a1.x,a1.x), pk2(a1.y,a1.y), pk2(a1.z,a1.z), pk2(a1.w,a1.w)
            };
            u64 bd[4] = { b0.x, b0.y, b1.x, b1.y };
#pragma unroll
            for (int i = 0; i < TM; i++) {
                fma2(acc[i][0], ad[i], bd[0]);
                fma2(acc[i][1], ad[i], bd[1]);
                fma2(acc[i][2], ad[i], bd[2]);
                fma2(acc[i][3], ad[i], bd[3]);
            }
        }
        if (kt + 1 < KT) {
            const int nb = buf ^ 1;
            As[nb][lc+0][lr]=ra0.x; As[nb][lc+1][lr]=ra0.y; As[nb][lc+2][lr]=ra0.z; As[nb][lc+3][lr]=ra0.w;
            As[nb][lc+4][lr]=ra1.x; As[nb][lc+5][lr]=ra1.y; As[nb][lc+6][lr]=ra1.z; As[nb][lc+7][lr]=ra1.w;
            Bs[nb][lc+0][lr]=rb0.x; Bs[nb][lc+1][lr]=rb0.y; Bs[nb][lc+2][lr]=rb0.z; Bs[nb][lc+3][lr]=rb0.w;
            Bs[nb][lc+4][lr]=rb1.x; Bs[nb][lc+5][lr]=rb1.y; Bs[nb][lc+6][lr]=rb1.z; Bs[nb][lc+7][lr]=rb1.w;
        }
        __syncthreads();
    }

#pragma unroll
    for (int i = 0; i < TM; i++) {
        const long rrow = bm + ty * TM + i;
        const long cb = bn + tx * TN;
        float o[8];
        upk2(acc[i][0], o[0], o[1]);
        upk2(acc[i][1], o[2], o[3]);
        upk2(acc[i][2], o[4], o[5]);
        upk2(acc[i][3], o[6], o[7]);
        const float* bp = bias + cb;
#pragma unroll
        for (int j = 0; j < 8; j++) {
            float v = o[j] + bp[j];
            o[j] = v;
            Oh[rrow * HID + cb + j] = __float2bfloat16(v);
        }
        *(float4*)(Of + rrow * HID + cb)     = make_float4(o[0], o[1], o[2], o[3]);
        *(float4*)(Of + rrow * HID + cb + 4) = make_float4(o[4], o[5], o[6], o[7]);
    }
}

// ============================================================================
// Scores GEMM via mma.sync (bf16, single pass): S = Qh Kh^T / 16  (R7-proven)
// Streaming stores (stcs) — S is consumed exactly once by rowtopk.
// ============================================================================
#define SPITCH 40

__global__ __launch_bounds__(256) void scores_kernel()
{
    __shared__ __align__(16) __nv_bfloat16 sA[2][128 * SPITCH];
    __shared__ __align__(16) __nv_bfloat16 sB[2][128 * SPITCH];

    const int tid = threadIdx.x;
    const int wid = tid >> 5, l = tid & 31;
    const int wm = wid & 1;
    const int wn = wid >> 1;
    const long b  = blockIdx.z;
    const long bm = (long)blockIdx.y * 128;
    const long bn = (long)blockIdx.x * 128;

    const uint32_t sAu = smem_u32(sA);
    const uint32_t sBu = smem_u32(sB);

    float cacc[4][4][4];
#pragma unroll
    for (int mi = 0; mi < 4; mi++)
#pragma unroll
        for (int ni = 0; ni < 4; ni++)
#pragma unroll
            for (int e = 0; e < 4; e++) cacc[mi][ni][e] = 0.f;

    auto fill = [&](int stage, int c) {
        const int kb = c * 64;   // 32 bf16 per chunk
        const char* Ag = (const char*)(d_Qh + (b * NN + bm) * HID) + kb;
        const char* Bg = (const char*)(d_Kh + (b * NN + bn) * HID) + kb;
        const uint32_t da = sAu + stage * (128 * SPITCH * 2);
        const uint32_t db = sBu + stage * (128 * SPITCH * 2);
#pragma unroll
        for (int i = 0; i < 2; i++) {
            const int idx = tid + i * 256;
            const int row = idx >> 2, ch = idx & 3;
            cp16(da + row * (SPITCH * 2) + ch * 16, Ag + (size_t)row * (HID * 2) + ch * 16);
            cp16(db + row * (SPITCH * 2) + ch * 16, Bg + (size_t)row * (HID * 2) + ch * 16);
        }
    };

    fill(0, 0);
    asm volatile("cp.async.commit_group;" ::: "memory");
    fill(1, 1);
    asm volatile("cp.async.commit_group;" ::: "memory");

    for (int c = 0; c < 8; c++) {
        const int s = c & 1;
        if (c < 6) asm volatile("cp.async.wait_group 1;" ::: "memory");
        else       asm volatile("cp.async.wait_group 0;" ::: "memory");
        __syncthreads();

        const uint32_t ab = sAu + s * (128 * SPITCH * 2);
        const uint32_t bb = sBu + s * (128 * SPITCH * 2);

        uint32_t af[2][4][4];
        uint32_t bf[2][2][4];
        const int rA = ((l >> 3) & 1) * 8 + (l & 7);
        const int cA = (l >> 4) * 16;
        const int rB = (l >> 4) * 8 + (l & 7);
        const int cB = ((l >> 3) & 1) * 16;
#pragma unroll
        for (int kk = 0; kk < 2; kk++) {
#pragma unroll
            for (int mi = 0; mi < 4; mi++)
                ldsm4(af[kk][mi],
                      ab + (uint32_t)(wm * 64 + mi * 16 + rA) * (SPITCH * 2) + kk * 32 + cA);
#pragma unroll
            for (int bi = 0; bi < 2; bi++)
                ldsm4(bf[kk][bi],
                      bb + (uint32_t)(wn * 32 + bi * 16 + rB) * (SPITCH * 2) + kk * 32 + cB);
        }
        __syncthreads();

        if (c + 2 < 8) {
            fill(s, c + 2);
            asm volatile("cp.async.commit_group;" ::: "memory");
        }

#pragma unroll
        for (int kk = 0; kk < 2; kk++)
#pragma unroll
            for (int mi = 0; mi < 4; mi++)
#pragma unroll
                for (int ni = 0; ni < 4; ni++) {
                    const int bi = ni >> 1, p = ni & 1;
                    mma_bf16(cacc[mi][ni], af[kk][mi],
                             bf[kk][bi][p * 2], bf[kk][bi][p * 2 + 1]);
                }
    }

    const int g = l >> 2, tg = l & 3;
#pragma unroll
    for (int mi = 0; mi < 4; mi++) {
        const long r0 = bm + wm * 64 + mi * 16 + g;
        float* S0 = d_Sg + ((size_t)(b * NN + r0)) * NN + bn + wn * 32;
        float* S1 = S0 + 8 * NN;
#pragma unroll
        for (int ni = 0; ni < 4; ni++) {
            const int co = ni * 8 + tg * 2;
            float2 v0 = { cacc[mi][ni][0] * 0.0625f, cacc[mi][ni][1] * 0.0625f };
            float2 v1 = { cacc[mi][ni][2] * 0.0625f, cacc[mi][ni][3] * 0.0625f };
            __stcs((float2*)(S0 + co), v0);
            __stcs((float2*)(S1 + co), v1);
        }
    }
}

// ============================================================================
// rowtopk v4: 512 threads, 8 elems/thread. Branch-free Batcher sort-8 of all
// elements (no insertion lists), REDUX block max, one exp pass for Z,
// R7-proven tournament extraction of top-16.
// ============================================================================
#define CSW(x, y) do { u64 _a = (x), _b = (y); \
    (x) = _a > _b ? _a : _b; (y) = _a > _b ? _b : _a; } while (0)

__device__ __forceinline__ void sort8(u64 a[8]) {
    CSW(a[0],a[1]); CSW(a[2],a[3]); CSW(a[4],a[5]); CSW(a[6],a[7]);
    CSW(a[0],a[2]); CSW(a[1],a[3]); CSW(a[4],a[6]); CSW(a[5],a[7]);
    CSW(a[1],a[2]); CSW(a[5],a[6]);
    CSW(a[0],a[4]); CSW(a[1],a[5]); CSW(a[2],a[6]); CSW(a[3],a[7]);
    CSW(a[2],a[4]); CSW(a[3],a[5]);
    CSW(a[1],a[2]); CSW(a[3],a[4]); CSW(a[5],a[6]);
}

__global__ __launch_bounds__(512) void rowtopk_kernel()
{
    const int row = blockIdx.x;
    const int tid = threadIdx.x, lid = tid & 31, wid = tid >> 5;   // 16 warps
    const float4* S4 = (const float4*)(d_Sg + (size_t)row * NN);

    __shared__ u64 lists[8][512];     // [slot][thread]
    __shared__ u64 wtop[16][16];      // per-warp top-16 (sorted desc)
    __shared__ uint32_t wred[16];
    __shared__ float wzs[16];

    float4 x0 = __ldcs(&S4[tid]);          // gi = tid*4 + e
    float4 x1 = __ldcs(&S4[tid + 512]);    // gi = 2048 + tid*4 + e
    float v[8] = { x0.x, x0.y, x0.z, x0.w, x1.x, x1.y, x1.z, x1.w };

    // thread max -> block max via REDUX
    float m = v[0];
#pragma unroll
    for (int i = 1; i < 8; i++) m = fmaxf(m, v[i]);
    {
        const uint32_t mk = __reduce_max_sync(0xFFFFFFFFu, mono_f(m));
        if (lid == 0) wred[wid] = mk;
    }
    __syncthreads();
    if (wid == 0) {
        uint32_t t = (lid < 16) ? wred[lid] : 0u;
        t = __reduce_max_sync(0xFFFFFFFFu, t);
        if (lid == 0) wred[0] = t;
    }
    __syncthreads();
    m = unmono_f(wred[0]);

    // Z with fixed block max
    float z = 0.f;
#pragma unroll
    for (int i = 0; i < 8; i++) z += __expf(v[i] - m);
#pragma unroll
    for (int o = 16; o; o >>= 1) z += __shfl_xor_sync(0xFFFFFFFFu, z, o);
    if (lid == 0) wzs[wid] = z;

    // build keys for all 8 elements, full branch-free sort
    u64 a[8];
#pragma unroll
    for (int i = 0; i < 8; i++) {
        const int gi = (i < 4) ? (tid * 4 + i) : (2048 + tid * 4 + (i - 4));
        a[i] = ((u64)mono_f(v[i]) << 32) | (unsigned)(4095 - gi);
    }
    sort8(a);

#pragma unroll
    for (int k = 0; k < 8; k++) lists[k][tid] = a[k];
    __syncwarp();

    // per-warp tournament: top-16 of the warp's 32 sorted-8 lists
    {
        int head = 0;
        u64 cur = a[0];
        for (int r = 0; r < 16; r++) {
            const uint32_t hi  = (uint32_t)(cur >> 32);
            const uint32_t win = __reduce_max_sync(0xFFFFFFFFu, hi);
            const uint32_t bal = __ballot_sync(0xFFFFFFFFu, hi == win);
            const int wl = __ffs(bal) - 1;
            if (lid == wl) {
                wtop[wid][r] = cur;
                head++;
                cur = (head < 8) ? lists[head][tid] : 0ULL;
            }
        }
    }
    __syncthreads();

    // final: warp 0 merges the 16 sorted-16 lists
    if (wid == 0) {
        int h = 0;
        u64 cur = (lid < 16) ? wtop[lid][0] : 0ULL;
        for (int r = 0; r < NCAND; r++) {
            const uint32_t hi  = (uint32_t)(cur >> 32);
            const uint32_t win = __reduce_max_sync(0xFFFFFFFFu, hi);
            const uint32_t bal = __ballot_sync(0xFFFFFFFFu, hi == win);
            const int wl = __ffs(bal) - 1;
            if (lid == wl) {
                d_C16[row * NCAND + r] = 4095 - (int)(cur & 0xFFFFFFFFu);
                h++;
                cur = (h < 16) ? wtop[lid][h] : 0ULL;
            }
        }
        if (lid == 0) {
            float Z = 0.f;
#pragma unroll
            for (int w = 0; w < 16; w++) Z += wzs[w];
            d_Mv[row] = m;
            d_Zv[row] = Z;
        }
    }
}

// ============================================================================
// rescore: fp32 SEQUENTIAL-k fma chain (R1/ref-matched). (R6/R7-proven)
// ============================================================================
__global__ __launch_bounds__(256) void rescore_kernel()
{
    __shared__ float sq[8][HID];
    const int wid = threadIdx.x >> 5, lane = threadIdx.x & 31;
    const int row = blockIdx.x * 8 + wid;
    const int b = row >> 12;

    for (int i = lane; i < HID; i += 32)
        sq[wid][i] = d_Qf[(size_t)row * HID + i];
    __syncwarp();

    float s = 0.f; int j = 0;
    if (lane < NCAND) {
        j = d_C16[row * NCAND + lane];
        const float* kr = d_Kf + ((size_t)((b << 12) + j)) * HID;
        float acc = 0.f;
#pragma unroll
        for (int k = 0; k < HID; k++)
            acc = fmaf(sq[wid][k], __ldg(kr + k), acc);
        s = acc * 0.0625f;
    }

    float scs[NCAND]; int ixs[NCAND];
#pragma unroll
    for (int c = 0; c < NCAND; c++) {
        scs[c] = __shfl_sync(0xFFFFFFFFu, s, c);
        ixs[c] = __shfl_sync(0xFFFFFFFFu, j, c);
    }

    if (lane == 0) {
        u64 key[NCAND];
#pragma unroll
        for (int c = 0; c < NCAND; c++)
            key[c] = ((u64)mono_f(scs[c]) << 32) | (unsigned)(4095 - ixs[c]);
        for (int i = 1; i < NCAND; i++) {
            u64 kv = key[i];
            int jj = i;
            while (jj > 0 && key[jj-1] < kv) { key[jj] = key[jj-1]; jj--; }
            key[jj] = kv;
        }
        const float m = d_Mv[row], z = d_Zv[row];
        float ev[KNN]; int oi[KNN]; float E8 = 0.f;
#pragma unroll
        for (int k = 0; k < KNN; k++) {
            const uint32_t mv = (uint32_t)(key[k] >> 32);
            const uint32_t u = (mv & 0x80000000u) ? (mv ^ 0x80000000u) : ~mv;
            const float sv = __uint_as_float(u);
            oi[k] = 4095 - (int)(key[k] & 0xFFFFFFFFu);
            ev[k] = __expf(sv - m);
            E8 += ev[k];
        }
        const float inv = 1.0f / (E8 + 1e-6f * z);
#pragma unroll
        for (int k = 0; k < KNN; k++) {
            d_TopV[row * KNN + k] = ev[k] * inv;
            d_TopI[row * KNN + k] = oi[k];
        }
    }
}

// ============================================================================
// Output: zero then symmetric sparse scatter (0.5*(A + A^T))
// ============================================================================
__global__ void zero_kernel(float* __restrict__ out)
{
    const size_t i = (size_t)blockIdx.x * blockDim.x + threadIdx.x;
    ((float4*)out)[i] = make_float4(0.f, 0.f, 0.f, 0.f);
}

__global__ void scatter_kernel(float* __restrict__ out)
{
    const int t = blockIdx.x * blockDim.x + threadIdx.x;
    if (t >= ROWS * KNN) return;
    const int row = t / KNN;
    const int b = row >> 12;
    const int i = row & (NN - 1);
    const int j = d_TopI[t];
    const float v = 0.5f * d_TopV[t];
    float* base = out + (size_t)b * NN * NN;
    atomicAdd(base + (size_t)i * NN + j, v);
    atomicAdd(base + (size_t)j * NN + i, v);
}

// ============================================================================
extern "C" void kernel_launch(void* const* d_in, const int* in_sizes, int n_in,
                              void* d_out, int out_size)
{
    const float* x  = (const float*)d_in[0];
    const float* Wq = (const float*)d_in[1];
    const float* bq = (const float*)d_in[2];
    const float* Wk = (const float*)d_in[3];
    const float* bk = (const float*)d_in[4];
    float* out = (float*)d_out;

    void *pqh, *pkh, *pqf, *pkf;
    cudaGetSymbolAddress(&pqh, d_Qh);
    cudaGetSymbolAddress(&pkh, d_Kh);
    cudaGetSymbolAddress(&pqf, d_Qf);
    cudaGetSymbolAddress(&pkf, d_Kf);

    // 1) projections -> fp32 + bf16
    dim3 gProj(HID / BN, ROWS / BM, 1);
    proj_kernel<<<gProj, 256>>>(x, Wq, bq, (float*)pqf, (__nv_bfloat16*)pqh);
    proj_kernel<<<gProj, 256>>>(x, Wk, bk, (float*)pkf, (__nv_bfloat16*)pkh);

    // 2) scores via mma.sync bf16 (single pass)
    dim3 gS(NN / 128, NN / 128, BATCH);
    scores_kernel<<<gS, 256>>>();

    // 3) approx (m, Z) + top-16 candidates (sort8 + tournament)
    rowtopk_kernel<<<ROWS, 512>>>();

    // 4) fp32 sequential-k rescoring + exact top-8 pick
    rescore_kernel<<<ROWS / 8, 256>>>();

    // 5) zero output, 6) symmetric sparse scatter
    zero_kernel<<<((size_t)BATCH * NN * NN / 4) / 256, 256>>>(out);
    scatter_kernel<<<(ROWS * KNN + 255) / 256, 256>>>(out);
}

// round 11
// speedup vs baseline: 1.4341x; 1.0829x over previous
#include <cuda_runtime.h>
#include <cuda_bf16.h>
#include <cstdint>

#define HID   256
#define NN    4096
#define BATCH 4
#define ROWS  (BATCH*NN)   // 16384
#define KNN   8
#define NCAND 16

// ---- scratch (static device globals; no runtime allocation) ----
__device__ __nv_bfloat16 d_Qh[(size_t)ROWS * HID];
__device__ __nv_bfloat16 d_Kh[(size_t)ROWS * HID];
__device__ float d_Qf[(size_t)ROWS * HID];
__device__ float d_Kf[(size_t)ROWS * HID];
__device__ float d_Sg[(size_t)BATCH * NN * NN];         // 268 MB
__device__ int   d_C16[ROWS * NCAND];
__device__ float d_Mv[ROWS];
__device__ float d_Zv[ROWS];
__device__ float d_TopV[ROWS * KNN];
__device__ int   d_TopI[ROWS * KNN];

typedef unsigned long long u64;

// ============================================================================
// PTX helpers (all sm_80-baseline)
// ============================================================================
__device__ __forceinline__ uint32_t smem_u32(const void* p) {
    uint32_t a;
    asm("{ .reg .u64 t; cvta.to.shared.u64 t, %1; cvt.u32.u64 %0, t; }" : "=r"(a) : "l"(p));
    return a;
}
__device__ __forceinline__ void cp16(uint32_t dst, const void* src) {
    asm volatile("cp.async.cg.shared.global [%0], [%1], 16;" :: "r"(dst), "l"(src));
}
__device__ __forceinline__ void ldsm4(uint32_t r[4], uint32_t addr) {
    asm volatile("ldmatrix.sync.aligned.m8n8.x4.shared.b16 {%0,%1,%2,%3}, [%4];"
                 : "=r"(r[0]), "=r"(r[1]), "=r"(r[2]), "=r"(r[3]) : "r"(addr));
}
__device__ __forceinline__ void mma_bf16(float c[4], const uint32_t a[4],
                                         uint32_t b0, uint32_t b1) {
    asm volatile(
        "mma.sync.aligned.m16n8k16.row.col.f32.bf16.bf16.f32 "
        "{%0,%1,%2,%3}, {%4,%5,%6,%7}, {%8,%9}, {%0,%1,%2,%3};"
        : "+f"(c[0]), "+f"(c[1]), "+f"(c[2]), "+f"(c[3])
        : "r"(a[0]), "r"(a[1]), "r"(a[2]), "r"(a[3]), "r"(b0), "r"(b1));
}
__device__ __forceinline__ u64 pk2(float lo, float hi) {
    u64 r;
    asm("mov.b64 %0, {%1, %2};" : "=l"(r) : "f"(lo), "f"(hi));
    return r;
}
__device__ __forceinline__ void upk2(u64 v, float& lo, float& hi) {
    asm("mov.b64 {%0, %1}, %2;" : "=f"(lo), "=f"(hi) : "l"(v));
}
__device__ __forceinline__ void fma2(u64& d, u64 a, u64 b) {
    asm("fma.rn.f32x2 %0, %1, %2, %0;" : "+l"(d) : "l"(a), "l"(b));
}
__device__ __forceinline__ uint32_t mono_f(float f) {
    uint32_t u = __float_as_uint(f);
    return (u & 0x80000000u) ? ~u : (u | 0x80000000u);
}
__device__ __forceinline__ float unmono_f(uint32_t m) {
    uint32_t u = (m & 0x80000000u) ? (m ^ 0x80000000u) : ~m;
    return __uint_as_float(u);
}

// ============================================================================
// Projection: O = x @ W^T + b -> fp32 copy + bf16 (hi only).  (R7-proven)
// ============================================================================
#define BM 128
#define BN 128
#define BK 16
#define TM 8
#define TN 8

__global__ __launch_bounds__(256, 2) void proj_kernel(
    const float* __restrict__ A, const float* __restrict__ B,
    const float* __restrict__ bias,
    float* __restrict__ Of, __nv_bfloat16* __restrict__ Oh)
{
    const int Kd = HID;
    const int tid = threadIdx.x;
    const int tx  = tid & 15;
    const int ty  = tid >> 4;
    const long bm = (long)blockIdx.y * BM;
    const long bn = (long)blockIdx.x * BN;

    __shared__ float As[2][BK][BM];
    __shared__ float Bs[2][BK][BN];

    u64 acc[TM][TN/2];
#pragma unroll
    for (int i = 0; i < TM; i++)
#pragma unroll
        for (int j = 0; j < TN/2; j++) acc[i][j] = 0ULL;

    const int lr = tid >> 1;
    const int lc = (tid & 1) * 8;
    const float* Abase = A + (bm + lr) * Kd + lc;
    const float* Bbase = B + (bn + lr) * Kd + lc;

    float4 ra0, ra1, rb0, rb1;
    ra0 = *(const float4*)(Abase);
    ra1 = *(const float4*)(Abase + 4);
    rb0 = *(const float4*)(Bbase);
    rb1 = *(const float4*)(Bbase + 4);
    {
        As[0][lc+0][lr]=ra0.x; As[0][lc+1][lr]=ra0.y; As[0][lc+2][lr]=ra0.z; As[0][lc+3][lr]=ra0.w;
        As[0][lc+4][lr]=ra1.x; As[0][lc+5][lr]=ra1.y; As[0][lc+6][lr]=ra1.z; As[0][lc+7][lr]=ra1.w;
        Bs[0][lc+0][lr]=rb0.x; Bs[0][lc+1][lr]=rb0.y; Bs[0][lc+2][lr]=rb0.z; Bs[0][lc+3][lr]=rb0.w;
        Bs[0][lc+4][lr]=rb1.x; Bs[0][lc+5][lr]=rb1.y; Bs[0][lc+6][lr]=rb1.z; Bs[0][lc+7][lr]=rb1.w;
    }
    __syncthreads();

    const int KT = Kd / BK;
    for (int kt = 0; kt < KT; ++kt) {
        const int buf = kt & 1;
        if (kt + 1 < KT) {
            const float* Ap = Abase + (kt + 1) * BK;
            const float* Bp = Bbase + (kt + 1) * BK;
            ra0 = *(const float4*)(Ap);  ra1 = *(const float4*)(Ap + 4);
            rb0 = *(const float4*)(Bp);  rb1 = *(const float4*)(Bp + 4);
        }
#pragma unroll
        for (int kk = 0; kk < BK; kk++) {
            float4 a0 = *(const float4*)&As[buf][kk][ty * TM];
            float4 a1 = *(const float4*)&As[buf][kk][ty * TM + 4];
            ulonglong2 b0 = *(const ulonglong2*)&Bs[buf][kk][tx * TN];
            ulonglong2 b1 = *(const ulonglong2*)&Bs[buf][kk][tx * TN + 4];
            u64 ad[TM] = {
                pk2(a0.x,a0.x), pk2(a0.y,a0.y), pk2(a0.z,a0.z), pk2(a0.w,a0.w),
                pk2(a1.x,a1.x), pk2(a1.y,a1.y), pk2(a1.z,a1.z), pk2(a1.w,a1.w)
            };
            u64 bd[4] = { b0.x, b0.y, b1.x, b1.y };
#pragma unroll
            for (int i = 0; i < TM; i++) {
                fma2(acc[i][0], ad[i], bd[0]);
                fma2(acc[i][1], ad[i], bd[1]);
                fma2(acc[i][2], ad[i], bd[2]);
                fma2(acc[i][3], ad[i], bd[3]);
            }
        }
        if (kt + 1 < KT) {
            const int nb = buf ^ 1;
            As[nb][lc+0][lr]=ra0.x; As[nb][lc+1][lr]=ra0.y; As[nb][lc+2][lr]=ra0.z; As[nb][lc+3][lr]=ra0.w;
            As[nb][lc+4][lr]=ra1.x; As[nb][lc+5][lr]=ra1.y; As[nb][lc+6][lr]=ra1.z; As[nb][lc+7][lr]=ra1.w;
            Bs[nb][lc+0][lr]=rb0.x; Bs[nb][lc+1][lr]=rb0.y; Bs[nb][lc+2][lr]=rb0.z; Bs[nb][lc+3][lr]=rb0.w;
            Bs[nb][lc+4][lr]=rb1.x; Bs[nb][lc+5][lr]=rb1.y; Bs[nb][lc+6][lr]=rb1.z; Bs[nb][lc+7][lr]=rb1.w;
        }
        __syncthreads();
    }

#pragma unroll
    for (int i = 0; i < TM; i++) {
        const long rrow = bm + ty * TM + i;
        const long cb = bn + tx * TN;
        float o[8];
        upk2(acc[i][0], o[0], o[1]);
        upk2(acc[i][1], o[2], o[3]);
        upk2(acc[i][2], o[4], o[5]);
        upk2(acc[i][3], o[6], o[7]);
        const float* bp = bias + cb;
#pragma unroll
        for (int j = 0; j < 8; j++) {
            float v = o[j] + bp[j];
            o[j] = v;
            Oh[rrow * HID + cb + j] = __float2bfloat16(v);
        }
        *(float4*)(Of + rrow * HID + cb)     = make_float4(o[0], o[1], o[2], o[3]);
        *(float4*)(Of + rrow * HID + cb + 4) = make_float4(o[4], o[5], o[6], o[7]);
    }
}

// ============================================================================
// Scores GEMM via mma.sync (bf16, single pass): S = Qh Kh^T / 16
// 3-stage cp.async pipeline, one sync per chunk, streaming fp32 stores.
// ============================================================================
#define SPITCH 40
#define SC_STG  10240                 // one stage of one matrix (128*40*2)
#define SC_SMEM (6 * SC_STG)          // 61440

__global__ __launch_bounds__(256) void scores_kernel()
{
    extern __shared__ __align__(16) char smem[];

    const int tid = threadIdx.x;
    const int wid = tid >> 5, l = tid & 31;
    const int wm = wid & 1;
    const int wn = wid >> 1;
    const long b  = blockIdx.z;
    const long bm = (long)blockIdx.y * 128;
    const long bn = (long)blockIdx.x * 128;

    const uint32_t sAu = smem_u32(smem);
    const uint32_t sBu = sAu + 3 * SC_STG;

    float cacc[4][4][4];
#pragma unroll
    for (int mi = 0; mi < 4; mi++)
#pragma unroll
        for (int ni = 0; ni < 4; ni++)
#pragma unroll
            for (int e = 0; e < 4; e++) cacc[mi][ni][e] = 0.f;

    auto fill = [&](int stage, int c) {
        const int kb = c * 64;   // 32 bf16 per chunk
        const char* Ag = (const char*)(d_Qh + (b * NN + bm) * HID) + kb;
        const char* Bg = (const char*)(d_Kh + (b * NN + bn) * HID) + kb;
        const uint32_t da = sAu + stage * SC_STG;
        const uint32_t db = sBu + stage * SC_STG;
#pragma unroll
        for (int i = 0; i < 2; i++) {
            const int idx = tid + i * 256;
            const int row = idx >> 2, ch = idx & 3;
            cp16(da + row * (SPITCH * 2) + ch * 16, Ag + (size_t)row * (HID * 2) + ch * 16);
            cp16(db + row * (SPITCH * 2) + ch * 16, Bg + (size_t)row * (HID * 2) + ch * 16);
        }
    };

    fill(0, 0);
    asm volatile("cp.async.commit_group;" ::: "memory");
    fill(1, 1);
    asm volatile("cp.async.commit_group;" ::: "memory");

    const int rA = ((l >> 3) & 1) * 8 + (l & 7);
    const int cA = (l >> 4) * 16;
    const int rB = (l >> 4) * 8 + (l & 7);
    const int cB = ((l >> 3) & 1) * 16;

    for (int c = 0; c < 8; c++) {
        const int s = c % 3;
        if (c < 7) asm volatile("cp.async.wait_group 1;" ::: "memory");
        else       asm volatile("cp.async.wait_group 0;" ::: "memory");
        __syncthreads();

        const uint32_t ab = sAu + s * SC_STG;
        const uint32_t bb = sBu + s * SC_STG;

        uint32_t af[2][4][4];
        uint32_t bf[2][2][4];
#pragma unroll
        for (int kk = 0; kk < 2; kk++) {
#pragma unroll
            for (int mi = 0; mi < 4; mi++)
                ldsm4(af[kk][mi],
                      ab + (uint32_t)(wm * 64 + mi * 16 + rA) * (SPITCH * 2) + kk * 32 + cA);
#pragma unroll
            for (int bi = 0; bi < 2; bi++)
                ldsm4(bf[kk][bi],
                      bb + (uint32_t)(wn * 32 + bi * 16 + rB) * (SPITCH * 2) + kk * 32 + cB);
        }

        if (c + 2 < 8) {
            fill((c + 2) % 3, c + 2);
            asm volatile("cp.async.commit_group;" ::: "memory");
        }

#pragma unroll
        for (int kk = 0; kk < 2; kk++)
#pragma unroll
            for (int mi = 0; mi < 4; mi++)
#pragma unroll
                for (int ni = 0; ni < 4; ni++) {
                    const int bi = ni >> 1, p = ni & 1;
                    mma_bf16(cacc[mi][ni], af[kk][mi],
                             bf[kk][bi][p * 2], bf[kk][bi][p * 2 + 1]);
                }
    }

    const int g = l >> 2, tg = l & 3;
#pragma unroll
    for (int mi = 0; mi < 4; mi++) {
        const long r0 = bm + wm * 64 + mi * 16 + g;
        float* S0 = d_Sg + ((size_t)(b * NN + r0)) * NN + bn + wn * 32;
        float* S1 = S0 + 8 * NN;
#pragma unroll
        for (int ni = 0; ni < 4; ni++) {
            const int co = ni * 8 + tg * 2;
            float2 v0 = { cacc[mi][ni][0] * 0.0625f, cacc[mi][ni][1] * 0.0625f };
            float2 v1 = { cacc[mi][ni][2] * 0.0625f, cacc[mi][ni][3] * 0.0625f };
            __stcs((float2*)(S0 + co), v0);
            __stcs((float2*)(S1 + co), v1);
        }
    }
}

// ============================================================================
// rowtopk v6: threshold prefilter (T = min of warp maxes => provable superset
// of block top-16), 512-entry survivor buffer (P(overflow) ~ 2e-13), and a
// TWO-STAGE tournament: warps 0-3 reduce 128 entries each to top-16, then
// warp 0 reduces the 64 semifinalists to the final 16.
// ============================================================================
#define CSW(x, y) do { u64 _a = (x), _b = (y); \
    (x) = _a > _b ? _a : _b; (y) = _a > _b ? _b : _a; } while (0)

__global__ __launch_bounds__(512) void rowtopk_kernel()
{
    const int row = blockIdx.x;
    const int tid = threadIdx.x, lid = tid & 31, wid = tid >> 5;   // 16 warps
    const float4* S4 = (const float4*)(d_Sg + (size_t)row * NN);

    __shared__ uint32_t wred[16];
    __shared__ float    wzs[16];
    __shared__ uint32_t bc[2];      // [0]=mono(block max), [1]=mono(T)
    __shared__ int      cnt;
    __shared__ u64      buf[512];
    __shared__ u64      sec[64];

    if (tid == 0) cnt = 0;

    float4 x0 = __ldcs(&S4[tid]);          // elems 4*tid + e
    float4 x1 = __ldcs(&S4[tid + 512]);    // elems 2048 + 4*tid + e
    float v[8] = { x0.x, x0.y, x0.z, x0.w, x1.x, x1.y, x1.z, x1.w };

    float tmax = v[0];
#pragma unroll
    for (int i = 1; i < 8; i++) tmax = fmaxf(tmax, v[i]);
    const uint32_t wm = __reduce_max_sync(0xFFFFFFFFu, mono_f(tmax));
    if (lid == 0) wred[wid] = wm;
    __syncthreads();

    if (wid == 0) {
        const uint32_t tlo = (lid < 16) ? wred[lid] : 0xFFFFFFFFu;
        const uint32_t tmin = __reduce_min_sync(0xFFFFFFFFu, tlo);
        const uint32_t thi = (lid < 16) ? wred[lid] : 0u;
        const uint32_t tmx = __reduce_max_sync(0xFFFFFFFFu, thi);
        if (lid == 0) { bc[0] = tmx; bc[1] = tmin; }
    }
    __syncthreads();
    const float m = unmono_f(bc[0]);
    const float T = unmono_f(bc[1]);

    // Z with fixed block max
    float z = 0.f;
#pragma unroll
    for (int i = 0; i < 8; i++) z += __expf(v[i] - m);
#pragma unroll
    for (int o = 16; o; o >>= 1) z += __shfl_xor_sync(0xFFFFFFFFu, z, o);
    if (lid == 0) wzs[wid] = z;

    // filter: keep v >= T (deterministic superset of block top-16)
#pragma unroll
    for (int i = 0; i < 8; i++) {
        if (v[i] >= T) {
            const int gi = (i < 4) ? (tid * 4 + i) : (2048 + tid * 4 + (i - 4));
            const int p = atomicAdd(&cnt, 1);
            if (p < 512)
                buf[p] = ((u64)mono_f(v[i]) << 32) | (unsigned)(4095 - gi);
        }
    }
    __syncthreads();
    const int n = min(cnt, 512);

    // ---- Stage A: warps 0-3 reduce buf[wid*128 .. +128) to top-16 ----
    if (wid < 4) {
        u64 a[4];
#pragma unroll
        for (int j = 0; j < 4; j++) {
            const int p = wid * 128 + lid + 32 * j;
            a[j] = (p < n) ? buf[p] : 0ULL;
        }
        CSW(a[0], a[1]); CSW(a[2], a[3]); CSW(a[0], a[2]); CSW(a[1], a[3]); CSW(a[1], a[2]);

        int h = 0;
        u64 cur = a[0];
        for (int r = 0; r < 16; r++) {
            const uint32_t hi  = (uint32_t)(cur >> 32);
            const uint32_t win = __reduce_max_sync(0xFFFFFFFFu, hi);
            const uint32_t bal = __ballot_sync(0xFFFFFFFFu, hi == win);
            const int wl = __ffs(bal) - 1;
            if (lid == wl) {
                sec[wid * 16 + r] = cur;
                h++;
                cur = (h < 4) ? a[h] : 0ULL;
            }
        }
    }
    __syncthreads();

    // ---- Stage B: warp 0 reduces the 64 semifinalists to top-16 ----
    if (wid == 0) {
        u64 a[2] = { sec[lid * 2], sec[lid * 2 + 1] };
        CSW(a[0], a[1]);

        int h = 0;
        u64 cur = a[0];
        for (int r = 0; r < NCAND; r++) {
            const uint32_t hi  = (uint32_t)(cur >> 32);
            const uint32_t win = __reduce_max_sync(0xFFFFFFFFu, hi);
            const uint32_t bal = __ballot_sync(0xFFFFFFFFu, hi == win);
            const int wl = __ffs(bal) - 1;
            if (lid == wl) {
                d_C16[row * NCAND + r] = 4095 - (int)(cur & 0xFFFFFFFFu);
                h++;
                cur = (h < 2) ? a[h] : 0ULL;
            }
        }
        if (lid == 0) {
            float Z = 0.f;
#pragma unroll
            for (int w = 0; w < 16; w++) Z += wzs[w];
            d_Mv[row] = m;
            d_Zv[row] = Z;
        }
    }
}

// ============================================================================
// rescore: fp32 SEQUENTIAL-k fma chain (R1/ref-matched). (R6-R9 proven)
// ============================================================================
__global__ __launch_bounds__(256) void rescore_kernel()
{
    __shared__ float sq[8][HID];
    const int wid = threadIdx.x >> 5, lane = threadIdx.x & 31;
    const int row = blockIdx.x * 8 + wid;
    const int b = row >> 12;

    for (int i = lane; i < HID; i += 32)
        sq[wid][i] = d_Qf[(size_t)row * HID + i];
    __syncwarp();

    float s = 0.f; int j = 0;
    if (lane < NCAND) {
        j = d_C16[row * NCAND + lane];
        const float* kr = d_Kf + ((size_t)((b << 12) + j)) * HID;
        float acc = 0.f;
#pragma unroll
        for (int k = 0; k < HID; k++)
            acc = fmaf(sq[wid][k], __ldg(kr + k), acc);
        s = acc * 0.0625f;
    }

    float scs[NCAND]; int ixs[NCAND];
#pragma unroll
    for (int c = 0; c < NCAND; c++) {
        scs[c] = __shfl_sync(0xFFFFFFFFu, s, c);
        ixs[c] = __shfl_sync(0xFFFFFFFFu, j, c);
    }

    if (lane == 0) {
        u64 key[NCAND];
#pragma unroll
        for (int c = 0; c < NCAND; c++)
            key[c] = ((u64)mono_f(scs[c]) << 32) | (unsigned)(4095 - ixs[c]);
        for (int i = 1; i < NCAND; i++) {
            u64 kv = key[i];
            int jj = i;
            while (jj > 0 && key[jj-1] < kv) { key[jj] = key[jj-1]; jj--; }
            key[jj] = kv;
        }
        const float m = d_Mv[row], z = d_Zv[row];
        float ev[KNN]; int oi[KNN]; float E8 = 0.f;
#pragma unroll
        for (int k = 0; k < KNN; k++) {
            const uint32_t mv = (uint32_t)(key[k] >> 32);
            const uint32_t u = (mv & 0x80000000u) ? (mv ^ 0x80000000u) : ~mv;
            const float sv = __uint_as_float(u);
            oi[k] = 4095 - (int)(key[k] & 0xFFFFFFFFu);
            ev[k] = __expf(sv - m);
            E8 += ev[k];
        }
        const float inv = 1.0f / (E8 + 1e-6f * z);
#pragma unroll
        for (int k = 0; k < KNN; k++) {
            d_TopV[row * KNN + k] = ev[k] * inv;
            d_TopI[row * KNN + k] = oi[k];
        }
    }
}

// ============================================================================
// Output: zero then symmetric sparse scatter (0.5*(A + A^T))
// ============================================================================
__global__ void zero_kernel(float* __restrict__ out)
{
    const size_t i = (size_t)blockIdx.x * blockDim.x + threadIdx.x;
    ((float4*)out)[i] = make_float4(0.f, 0.f, 0.f, 0.f);
}

__global__ void scatter_kernel(float* __restrict__ out)
{
    const int t = blockIdx.x * blockDim.x + threadIdx.x;
    if (t >= ROWS * KNN) return;
    const int row = t / KNN;
    const int b = row >> 12;
    const int i = row & (NN - 1);
    const int j = d_TopI[t];
    const float v = 0.5f * d_TopV[t];
    float* base = out + (size_t)b * NN * NN;
    atomicAdd(base + (size_t)i * NN + j, v);
    atomicAdd(base + (size_t)j * NN + i, v);
}

// ============================================================================
extern "C" void kernel_launch(void* const* d_in, const int* in_sizes, int n_in,
                              void* d_out, int out_size)
{
    const float* x  = (const float*)d_in[0];
    const float* Wq = (const float*)d_in[1];
    const float* bq = (const float*)d_in[2];
    const float* Wk = (const float*)d_in[3];
    const float* bk = (const float*)d_in[4];
    float* out = (float*)d_out;

    void *pqh, *pkh, *pqf, *pkf;
    cudaGetSymbolAddress(&pqh, d_Qh);
    cudaGetSymbolAddress(&pkh, d_Kh);
    cudaGetSymbolAddress(&pqf, d_Qf);
    cudaGetSymbolAddress(&pkf, d_Kf);

    cudaFuncSetAttribute(scores_kernel,
                         cudaFuncAttributeMaxDynamicSharedMemorySize, SC_SMEM);

    // 1) projections -> fp32 + bf16
    dim3 gProj(HID / BN, ROWS / BM, 1);
    proj_kernel<<<gProj, 256>>>(x, Wq, bq, (float*)pqf, (__nv_bfloat16*)pqh);
    proj_kernel<<<gProj, 256>>>(x, Wk, bk, (float*)pkf, (__nv_bfloat16*)pkh);

    // 2) scores via mma.sync bf16 (single pass, 3-stage pipeline)
    dim3 gS(NN / 128, NN / 128, BATCH);
    scores_kernel<<<gS, 256, SC_SMEM>>>();

    // 3) (m, Z) + top-16 candidates via threshold prefilter + 2-stage tournament
    rowtopk_kernel<<<ROWS, 512>>>();

    // 4) fp32 sequential-k rescoring + exact top-8 pick
    rescore_kernel<<<ROWS / 8, 256>>>();

    // 5) zero output, 6) symmetric sparse scatter
    zero_kernel<<<((size_t)BATCH * NN * NN / 4) / 256, 256>>>(out);
    scatter_kernel<<<(ROWS * KNN + 255) / 256, 256>>>(out);
}

// round 12
// speedup vs baseline: 1.4476x; 1.0094x over previous
#include <cuda_runtime.h>
#include <cuda_bf16.h>
#include <cstdint>

#define HID   256
#define NN    4096
#define BATCH 4
#define ROWS  (BATCH*NN)   // 16384
#define KNN   8
#define NCAND 16

// ---- scratch (static device globals; no runtime allocation) ----
__device__ __nv_bfloat16 d_Qh[(size_t)ROWS * HID];
__device__ __nv_bfloat16 d_Kh[(size_t)ROWS * HID];
__device__ float d_Qf[(size_t)ROWS * HID];
__device__ float d_Kf[(size_t)ROWS * HID];
__device__ __nv_bfloat16 d_Sb[(size_t)BATCH * NN * NN];   // 134 MB (bf16 scores)
__device__ int   d_C16[ROWS * NCAND];
__device__ float d_Mv[ROWS];
__device__ float d_Zv[ROWS];
__device__ float d_TopV[ROWS * KNN];
__device__ int   d_TopI[ROWS * KNN];

typedef unsigned long long u64;

// ============================================================================
// PTX helpers (all sm_80-baseline)
// ============================================================================
__device__ __forceinline__ uint32_t smem_u32(const void* p) {
    uint32_t a;
    asm("{ .reg .u64 t; cvta.to.shared.u64 t, %1; cvt.u32.u64 %0, t; }" : "=r"(a) : "l"(p));
    return a;
}
__device__ __forceinline__ void cp16(uint32_t dst, const void* src) {
    asm volatile("cp.async.cg.shared.global [%0], [%1], 16;" :: "r"(dst), "l"(src));
}
__device__ __forceinline__ void ldsm4(uint32_t r[4], uint32_t addr) {
    asm volatile("ldmatrix.sync.aligned.m8n8.x4.shared.b16 {%0,%1,%2,%3}, [%4];"
                 : "=r"(r[0]), "=r"(r[1]), "=r"(r[2]), "=r"(r[3]) : "r"(addr));
}
__device__ __forceinline__ void mma_bf16(float c[4], const uint32_t a[4],
                                         uint32_t b0, uint32_t b1) {
    asm volatile(
        "mma.sync.aligned.m16n8k16.row.col.f32.bf16.bf16.f32 "
        "{%0,%1,%2,%3}, {%4,%5,%6,%7}, {%8,%9}, {%0,%1,%2,%3};"
        : "+f"(c[0]), "+f"(c[1]), "+f"(c[2]), "+f"(c[3])
        : "r"(a[0]), "r"(a[1]), "r"(a[2]), "r"(a[3]), "r"(b0), "r"(b1));
}
__device__ __forceinline__ u64 pk2(float lo, float hi) {
    u64 r;
    asm("mov.b64 %0, {%1, %2};" : "=l"(r) : "f"(lo), "f"(hi));
    return r;
}
__device__ __forceinline__ void upk2(u64 v, float& lo, float& hi) {
    asm("mov.b64 {%0, %1}, %2;" : "=f"(lo), "=f"(hi) : "l"(v));
}
__device__ __forceinline__ void fma2(u64& d, u64 a, u64 b) {
    asm("fma.rn.f32x2 %0, %1, %2, %0;" : "+l"(d) : "l"(a), "l"(b));
}
__device__ __forceinline__ uint32_t mono_f(float f) {
    uint32_t u = __float_as_uint(f);
    return (u & 0x80000000u) ? ~u : (u | 0x80000000u);
}
__device__ __forceinline__ float unmono_f(uint32_t m) {
    uint32_t u = (m & 0x80000000u) ? (m ^ 0x80000000u) : ~m;
    return __uint_as_float(u);
}
__device__ __forceinline__ uint32_t bfpack(float a, float b) {
    uint32_t r;
    asm("cvt.rn.bf16x2.f32 %0, %2, %1;" : "=r"(r) : "f"(a), "f"(b));
    return r;   // low half = a, high half = b
}

// ============================================================================
// Projection (merged Q/K via blockIdx.z): O = x @ W^T + b -> fp32 + bf16.
// ============================================================================
#define BM 128
#define BN 128
#define BK 16
#define TM 8
#define TN 8

__global__ __launch_bounds__(256, 2) void proj_kernel(
    const float* __restrict__ A,
    const float* __restrict__ Wq, const float* __restrict__ bq,
    const float* __restrict__ Wk, const float* __restrict__ bk,
    float* __restrict__ Qf, __nv_bfloat16* __restrict__ Qh,
    float* __restrict__ Kf, __nv_bfloat16* __restrict__ Kh)
{
    const float* B  = blockIdx.z ? Wk : Wq;
    const float* bias = blockIdx.z ? bk : bq;
    float* Of = blockIdx.z ? Kf : Qf;
    __nv_bfloat16* Oh = blockIdx.z ? Kh : Qh;

    const int Kd = HID;
    const int tid = threadIdx.x;
    const int tx  = tid & 15;
    const int ty  = tid >> 4;
    const long bm = (long)blockIdx.y * BM;
    const long bn = (long)blockIdx.x * BN;

    __shared__ float As[2][BK][BM];
    __shared__ float Bs[2][BK][BN];

    u64 acc[TM][TN/2];
#pragma unroll
    for (int i = 0; i < TM; i++)
#pragma unroll
        for (int j = 0; j < TN/2; j++) acc[i][j] = 0ULL;

    const int lr = tid >> 1;
    const int lc = (tid & 1) * 8;
    const float* Abase = A + (bm + lr) * Kd + lc;
    const float* Bbase = B + (bn + lr) * Kd + lc;

    float4 ra0, ra1, rb0, rb1;
    ra0 = *(const float4*)(Abase);
    ra1 = *(const float4*)(Abase + 4);
    rb0 = *(const float4*)(Bbase);
    rb1 = *(const float4*)(Bbase + 4);
    {
        As[0][lc+0][lr]=ra0.x; As[0][lc+1][lr]=ra0.y; As[0][lc+2][lr]=ra0.z; As[0][lc+3][lr]=ra0.w;
        As[0][lc+4][lr]=ra1.x; As[0][lc+5][lr]=ra1.y; As[0][lc+6][lr]=ra1.z; As[0][lc+7][lr]=ra1.w;
        Bs[0][lc+0][lr]=rb0.x; Bs[0][lc+1][lr]=rb0.y; Bs[0][lc+2][lr]=rb0.z; Bs[0][lc+3][lr]=rb0.w;
        Bs[0][lc+4][lr]=rb1.x; Bs[0][lc+5][lr]=rb1.y; Bs[0][lc+6][lr]=rb1.z; Bs[0][lc+7][lr]=rb1.w;
    }
    __syncthreads();

    const int KT = Kd / BK;
    for (int kt = 0; kt < KT; ++kt) {
        const int buf = kt & 1;
        if (kt + 1 < KT) {
            const float* Ap = Abase + (kt + 1) * BK;
            const float* Bp = Bbase + (kt + 1) * BK;
            ra0 = *(const float4*)(Ap);  ra1 = *(const float4*)(Ap + 4);
            rb0 = *(const float4*)(Bp);  rb1 = *(const float4*)(Bp + 4);
        }
#pragma unroll
        for (int kk = 0; kk < BK; kk++) {
            float4 a0 = *(const float4*)&As[buf][kk][ty * TM];
            float4 a1 = *(const float4*)&As[buf][kk][ty * TM + 4];
            ulonglong2 b0 = *(const ulonglong2*)&Bs[buf][kk][tx * TN];
            ulonglong2 b1 = *(const ulonglong2*)&Bs[buf][kk][tx * TN + 4];
            u64 ad[TM] = {
                pk2(a0.x,a0.x), pk2(a0.y,a0.y), pk2(a0.z,a0.z), pk2(a0.w,a0.w),
                pk2(a1.x,a1.x), pk2(a1.y,a1.y), pk2(a1.z,a1.z), pk2(a1.w,a1.w)
            };
            u64 bd[4] = { b0.x, b0.y, b1.x, b1.y };
#pragma unroll
            for (int i = 0; i < TM; i++) {
                fma2(acc[i][0], ad[i], bd[0]);
                fma2(acc[i][1], ad[i], bd[1]);
                fma2(acc[i][2], ad[i], bd[2]);
                fma2(acc[i][3], ad[i], bd[3]);
            }
        }
        if (kt + 1 < KT) {
            const int nb = buf ^ 1;
            As[nb][lc+0][lr]=ra0.x; As[nb][lc+1][lr]=ra0.y; As[nb][lc+2][lr]=ra0.z; As[nb][lc+3][lr]=ra0.w;
            As[nb][lc+4][lr]=ra1.x; As[nb][lc+5][lr]=ra1.y; As[nb][lc+6][lr]=ra1.z; As[nb][lc+7][lr]=ra1.w;
            Bs[nb][lc+0][lr]=rb0.x; Bs[nb][lc+1][lr]=rb0.y; Bs[nb][lc+2][lr]=rb0.z; Bs[nb][lc+3][lr]=rb0.w;
            Bs[nb][lc+4][lr]=rb1.x; Bs[nb][lc+5][lr]=rb1.y; Bs[nb][lc+6][lr]=rb1.z; Bs[nb][lc+7][lr]=rb1.w;
        }
        __syncthreads();
    }

#pragma unroll
    for (int i = 0; i < TM; i++) {
        const long rrow = bm + ty * TM + i;
        const long cb = bn + tx * TN;
        float o[8];
        upk2(acc[i][0], o[0], o[1]);
        upk2(acc[i][1], o[2], o[3]);
        upk2(acc[i][2], o[4], o[5]);
        upk2(acc[i][3], o[6], o[7]);
        const float* bp = bias + cb;
#pragma unroll
        for (int j = 0; j < 8; j++) {
            float v = o[j] + bp[j];
            o[j] = v;
            Oh[rrow * HID + cb + j] = __float2bfloat16(v);
        }
        *(float4*)(Of + rrow * HID + cb)     = make_float4(o[0], o[1], o[2], o[3]);
        *(float4*)(Of + rrow * HID + cb + 4) = make_float4(o[4], o[5], o[6], o[7]);
    }
}

// ============================================================================
// Scores GEMM via mma.sync (bf16, single pass): S = Qh Kh^T / 16
// 3-stage cp.async pipeline; stores S as bf16 (halves traffic).
// ============================================================================
#define SPITCH 40
#define SC_STG  10240                 // one stage of one matrix (128*40*2)
#define SC_SMEM (6 * SC_STG)          // 61440

__global__ __launch_bounds__(256) void scores_kernel()
{
    extern __shared__ __align__(16) char smem[];

    const int tid = threadIdx.x;
    const int wid = tid >> 5, l = tid & 31;
    const int wm = wid & 1;
    const int wn = wid >> 1;
    const long b  = blockIdx.z;
    const long bm = (long)blockIdx.y * 128;
    const long bn = (long)blockIdx.x * 128;

    const uint32_t sAu = smem_u32(smem);
    const uint32_t sBu = sAu + 3 * SC_STG;

    float cacc[4][4][4];
#pragma unroll
    for (int mi = 0; mi < 4; mi++)
#pragma unroll
        for (int ni = 0; ni < 4; ni++)
#pragma unroll
            for (int e = 0; e < 4; e++) cacc[mi][ni][e] = 0.f;

    auto fill = [&](int stage, int c) {
        const int kb = c * 64;   // 32 bf16 per chunk
        const char* Ag = (const char*)(d_Qh + (b * NN + bm) * HID) + kb;
        const char* Bg = (const char*)(d_Kh + (b * NN + bn) * HID) + kb;
        const uint32_t da = sAu + stage * SC_STG;
        const uint32_t db = sBu + stage * SC_STG;
#pragma unroll
        for (int i = 0; i < 2; i++) {
            const int idx = tid + i * 256;
            const int row = idx >> 2, ch = idx & 3;
            cp16(da + row * (SPITCH * 2) + ch * 16, Ag + (size_t)row * (HID * 2) + ch * 16);
            cp16(db + row * (SPITCH * 2) + ch * 16, Bg + (size_t)row * (HID * 2) + ch * 16);
        }
    };

    fill(0, 0);
    asm volatile("cp.async.commit_group;" ::: "memory");
    fill(1, 1);
    asm volatile("cp.async.commit_group;" ::: "memory");

    const int rA = ((l >> 3) & 1) * 8 + (l & 7);
    const int cA = (l >> 4) * 16;
    const int rB = (l >> 4) * 8 + (l & 7);
    const int cB = ((l >> 3) & 1) * 16;

    for (int c = 0; c < 8; c++) {
        const int s = c % 3;
        if (c < 7) asm volatile("cp.async.wait_group 1;" ::: "memory");
        else       asm volatile("cp.async.wait_group 0;" ::: "memory");
        __syncthreads();

        const uint32_t ab = sAu + s * SC_STG;
        const uint32_t bb = sBu + s * SC_STG;

        uint32_t af[2][4][4];
        uint32_t bf[2][2][4];
#pragma unroll
        for (int kk = 0; kk < 2; kk++) {
#pragma unroll
            for (int mi = 0; mi < 4; mi++)
                ldsm4(af[kk][mi],
                      ab + (uint32_t)(wm * 64 + mi * 16 + rA) * (SPITCH * 2) + kk * 32 + cA);
#pragma unroll
            for (int bi = 0; bi < 2; bi++)
                ldsm4(bf[kk][bi],
                      bb + (uint32_t)(wn * 32 + bi * 16 + rB) * (SPITCH * 2) + kk * 32 + cB);
        }

        if (c + 2 < 8) {
            fill((c + 2) % 3, c + 2);
            asm volatile("cp.async.commit_group;" ::: "memory");
        }

#pragma unroll
        for (int kk = 0; kk < 2; kk++)
#pragma unroll
            for (int mi = 0; mi < 4; mi++)
#pragma unroll
                for (int ni = 0; ni < 4; ni++) {
                    const int bi = ni >> 1, p = ni & 1;
                    mma_bf16(cacc[mi][ni], af[kk][mi],
                             bf[kk][bi][p * 2], bf[kk][bi][p * 2 + 1]);
                }
    }

    const int g = l >> 2, tg = l & 3;
#pragma unroll
    for (int mi = 0; mi < 4; mi++) {
        const long r0 = bm + wm * 64 + mi * 16 + g;
        __nv_bfloat16* S0 = d_Sb + ((size_t)(b * NN + r0)) * NN + bn + wn * 32;
        __nv_bfloat16* S1 = S0 + 8 * NN;
#pragma unroll
        for (int ni = 0; ni < 4; ni++) {
            const int co = ni * 8 + tg * 2;
            const uint32_t p0 = bfpack(cacc[mi][ni][0] * 0.0625f, cacc[mi][ni][1] * 0.0625f);
            const uint32_t p1 = bfpack(cacc[mi][ni][2] * 0.0625f, cacc[mi][ni][3] * 0.0625f);
            __stcs((uint32_t*)(S0 + co), p0);
            __stcs((uint32_t*)(S1 + co), p1);
        }
    }
}

// ============================================================================
// rowtopk v7 (bf16 input): threshold prefilter (T = min of warp maxes =>
// provable superset of block top-16), 512-entry buffer, 2-stage tournament.
// One 16B ldcs per thread (8 bf16).
// ============================================================================
#define CSW(x, y) do { u64 _a = (x), _b = (y); \
    (x) = _a > _b ? _a : _b; (y) = _a > _b ? _b : _a; } while (0)

__global__ __launch_bounds__(512) void rowtopk_kernel()
{
    const int row = blockIdx.x;
    const int tid = threadIdx.x, lid = tid & 31, wid = tid >> 5;   // 16 warps
    const uint4* S16 = (const uint4*)(d_Sb + (size_t)row * NN);

    __shared__ uint32_t wred[16];
    __shared__ float    wzs[16];
    __shared__ uint32_t bc[2];      // [0]=mono(block max), [1]=mono(T)
    __shared__ int      cnt;
    __shared__ u64      buf[512];
    __shared__ u64      sec[64];

    if (tid == 0) cnt = 0;

    const uint4 q = __ldcs(&S16[tid]);     // 8 bf16: elems 8*tid .. 8*tid+7
    float v[8];
    {
        const uint32_t w[4] = { q.x, q.y, q.z, q.w };
#pragma unroll
        for (int p = 0; p < 4; p++) {
            const __nv_bfloat162 h2 = *(const __nv_bfloat162*)&w[p];
            v[2*p]   = __bfloat162float(__low2bfloat16(h2));
            v[2*p+1] = __bfloat162float(__high2bfloat16(h2));
        }
    }

    float tmax = v[0];
#pragma unroll
    for (int i = 1; i < 8; i++) tmax = fmaxf(tmax, v[i]);
    const uint32_t wm = __reduce_max_sync(0xFFFFFFFFu, mono_f(tmax));
    if (lid == 0) wred[wid] = wm;
    __syncthreads();

    if (wid == 0) {
        const uint32_t tlo = (lid < 16) ? wred[lid] : 0xFFFFFFFFu;
        const uint32_t tmin = __reduce_min_sync(0xFFFFFFFFu, tlo);
        const uint32_t thi = (lid < 16) ? wred[lid] : 0u;
        const uint32_t tmx = __reduce_max_sync(0xFFFFFFFFu, thi);
        if (lid == 0) { bc[0] = tmx; bc[1] = tmin; }
    }
    __syncthreads();
    const float m = unmono_f(bc[0]);
    const float T = unmono_f(bc[1]);

    // Z with fixed block max
    float z = 0.f;
#pragma unroll
    for (int i = 0; i < 8; i++) z += __expf(v[i] - m);
#pragma unroll
    for (int o = 16; o; o >>= 1) z += __shfl_xor_sync(0xFFFFFFFFu, z, o);
    if (lid == 0) wzs[wid] = z;

    // filter: keep v >= T (deterministic superset of block top-16)
#pragma unroll
    for (int i = 0; i < 8; i++) {
        if (v[i] >= T) {
            const int gi = tid * 8 + i;
            const int p = atomicAdd(&cnt, 1);
            if (p < 512)
                buf[p] = ((u64)mono_f(v[i]) << 32) | (unsigned)(4095 - gi);
        }
    }
    __syncthreads();
    const int n = min(cnt, 512);

    // ---- Stage A: warps 0-3 reduce buf[wid*128 .. +128) to top-16 ----
    if (wid < 4) {
        u64 a[4];
#pragma unroll
        for (int j = 0; j < 4; j++) {
            const int p = wid * 128 + lid + 32 * j;
            a[j] = (p < n) ? buf[p] : 0ULL;
        }
        CSW(a[0], a[1]); CSW(a[2], a[3]); CSW(a[0], a[2]); CSW(a[1], a[3]); CSW(a[1], a[2]);

        int h = 0;
        u64 cur = a[0];
        for (int r = 0; r < 16; r++) {
            const uint32_t hi  = (uint32_t)(cur >> 32);
            const uint32_t win = __reduce_max_sync(0xFFFFFFFFu, hi);
            const uint32_t bal = __ballot_sync(0xFFFFFFFFu, hi == win);
            const int wl = __ffs(bal) - 1;
            if (lid == wl) {
                sec[wid * 16 + r] = cur;
                h++;
                cur = (h < 4) ? a[h] : 0ULL;
            }
        }
    }
    __syncthreads();

    // ---- Stage B: warp 0 reduces the 64 semifinalists to top-16 ----
    if (wid == 0) {
        u64 a[2] = { sec[lid * 2], sec[lid * 2 + 1] };
        CSW(a[0], a[1]);

        int h = 0;
        u64 cur = a[0];
        for (int r = 0; r < NCAND; r++) {
            const uint32_t hi  = (uint32_t)(cur >> 32);
            const uint32_t win = __reduce_max_sync(0xFFFFFFFFu, hi);
            const uint32_t bal = __ballot_sync(0xFFFFFFFFu, hi == win);
            const int wl = __ffs(bal) - 1;
            if (lid == wl) {
                d_C16[row * NCAND + r] = 4095 - (int)(cur & 0xFFFFFFFFu);
                h++;
                cur = (h < 2) ? a[h] : 0ULL;
            }
        }
        if (lid == 0) {
            float Z = 0.f;
#pragma unroll
            for (int w = 0; w < 16; w++) Z += wzs[w];
            d_Mv[row] = m;
            d_Zv[row] = Z;
        }
    }
}

// ============================================================================
// rescore: fp32 SEQUENTIAL-k fma chain (R1/ref-matched). (R6-R11 proven)
// ============================================================================
__global__ __launch_bounds__(256) void rescore_kernel()
{
    __shared__ float sq[8][HID];
    const int wid = threadIdx.x >> 5, lane = threadIdx.x & 31;
    const int row = blockIdx.x * 8 + wid;
    const int b = row >> 12;

    for (int i = lane; i < HID; i += 32)
        sq[wid][i] = d_Qf[(size_t)row * HID + i];
    __syncwarp();

    float s = 0.f; int j = 0;
    if (lane < NCAND) {
        j = d_C16[row * NCAND + lane];
        const float* kr = d_Kf + ((size_t)((b << 12) + j)) * HID;
        float acc = 0.f;
#pragma unroll
        for (int k = 0; k < HID; k++)
            acc = fmaf(sq[wid][k], __ldg(kr + k), acc);
        s = acc * 0.0625f;
    }

    float scs[NCAND]; int ixs[NCAND];
#pragma unroll
    for (int c = 0; c < NCAND; c++) {
        scs[c] = __shfl_sync(0xFFFFFFFFu, s, c);
        ixs[c] = __shfl_sync(0xFFFFFFFFu, j, c);
    }

    if (lane == 0) {
        u64 key[NCAND];
#pragma unroll
        for (int c = 0; c < NCAND; c++)
            key[c] = ((u64)mono_f(scs[c]) << 32) | (unsigned)(4095 - ixs[c]);
        for (int i = 1; i < NCAND; i++) {
            u64 kv = key[i];
            int jj = i;
            while (jj > 0 && key[jj-1] < kv) { key[jj] = key[jj-1]; jj--; }
            key[jj] = kv;
        }
        const float m = d_Mv[row], z = d_Zv[row];
        float ev[KNN]; int oi[KNN]; float E8 = 0.f;
#pragma unroll
        for (int k = 0; k < KNN; k++) {
            const uint32_t mv = (uint32_t)(key[k] >> 32);
            const uint32_t u = (mv & 0x80000000u) ? (mv ^ 0x80000000u) : ~mv;
            const float sv = __uint_as_float(u);
            oi[k] = 4095 - (int)(key[k] & 0xFFFFFFFFu);
            ev[k] = __expf(sv - m);
            E8 += ev[k];
        }
        const float inv = 1.0f / (E8 + 1e-6f * z);
#pragma unroll
        for (int k = 0; k < KNN; k++) {
            d_TopV[row * KNN + k] = ev[k] * inv;
            d_TopI[row * KNN + k] = oi[k];
        }
    }
}

// ============================================================================
// Output: zero then symmetric sparse scatter (0.5*(A + A^T))
// ============================================================================
__global__ void zero_kernel(float* __restrict__ out)
{
    const size_t i = (size_t)blockIdx.x * blockDim.x + threadIdx.x;
    ((float4*)out)[i] = make_float4(0.f, 0.f, 0.f, 0.f);
}

__global__ void scatter_kernel(float* __restrict__ out)
{
    const int t = blockIdx.x * blockDim.x + threadIdx.x;
    if (t >= ROWS * KNN) return;
    const int row = t / KNN;
    const int b = row >> 12;
    const int i = row & (NN - 1);
    const int j = d_TopI[t];
    const float v = 0.5f * d_TopV[t];
    float* base = out + (size_t)b * NN * NN;
    atomicAdd(base + (size_t)i * NN + j, v);
    atomicAdd(base + (size_t)j * NN + i, v);
}

// ============================================================================
extern "C" void kernel_launch(void* const* d_in, const int* in_sizes, int n_in,
                              void* d_out, int out_size)
{
    const float* x  = (const float*)d_in[0];
    const float* Wq = (const float*)d_in[1];
    const float* bq = (const float*)d_in[2];
    const float* Wk = (const float*)d_in[3];
    const float* bk = (const float*)d_in[4];
    float* out = (float*)d_out;

    void *pqh, *pkh, *pqf, *pkf;
    cudaGetSymbolAddress(&pqh, d_Qh);
    cudaGetSymbolAddress(&pkh, d_Kh);
    cudaGetSymbolAddress(&pqf, d_Qf);
    cudaGetSymbolAddress(&pkf, d_Kf);

    cudaFuncSetAttribute(scores_kernel,
                         cudaFuncAttributeMaxDynamicSharedMemorySize, SC_SMEM);

    // 1) projections (Q and K in one launch via blockIdx.z)
    dim3 gProj(HID / BN, ROWS / BM, 2);
    proj_kernel<<<gProj, 256>>>(x, Wq, bq, Wk, bk,
                                (float*)pqf, (__nv_bfloat16*)pqh,
                                (float*)pkf, (__nv_bfloat16*)pkh);

    // 2) scores via mma.sync bf16 (single pass, 3-stage pipeline, bf16 out)
    dim3 gS(NN / 128, NN / 128, BATCH);
    scores_kernel<<<gS, 256, SC_SMEM>>>();

    // 3) (m, Z) + top-16 candidates via threshold prefilter + 2-stage tournament
    rowtopk_kernel<<<ROWS, 512>>>();

    // 4) fp32 sequential-k rescoring + exact top-8 pick
    rescore_kernel<<<ROWS / 8, 256>>>();

    // 5) zero output, 6) symmetric sparse scatter
    zero_kernel<<<((size_t)BATCH * NN * NN / 4) / 256, 256>>>(out);
    scatter_kernel<<<(ROWS * KNN + 255) / 256, 256>>>(out);
}

// round 13
// speedup vs baseline: 1.8929x; 1.3076x over previous
#include <cuda_runtime.h>
#include <cuda_bf16.h>
#include <cstdint>

#define HID   256
#define NN    4096
#define BATCH 4
#define ROWS  (BATCH*NN)   // 16384
#define KNN   8
#define NCAND 16

// ---- scratch (static device globals; no runtime allocation) ----
__device__ __nv_bfloat16 d_Qh[(size_t)ROWS * HID];
__device__ __nv_bfloat16 d_Kh[(size_t)ROWS * HID];
__device__ float d_Qf[(size_t)ROWS * HID];
__device__ float d_Kf[(size_t)ROWS * HID];
__device__ __nv_bfloat16 d_Sb[(size_t)BATCH * NN * NN];   // 134 MB (bf16 scores)
__device__ int   d_C16[ROWS * NCAND];
__device__ float d_Mv[ROWS];
__device__ float d_Zv[ROWS];
__device__ float d_TopV[ROWS * KNN];
__device__ int   d_TopI[ROWS * KNN];

typedef unsigned long long u64;

// ============================================================================
// PTX helpers (all sm_80-baseline)
// ============================================================================
__device__ __forceinline__ uint32_t smem_u32(const void* p) {
    uint32_t a;
    asm("{ .reg .u64 t; cvta.to.shared.u64 t, %1; cvt.u32.u64 %0, t; }" : "=r"(a) : "l"(p));
    return a;
}
__device__ __forceinline__ void cp16(uint32_t dst, const void* src) {
    asm volatile("cp.async.cg.shared.global [%0], [%1], 16;" :: "r"(dst), "l"(src));
}
__device__ __forceinline__ void ldsm4(uint32_t r[4], uint32_t addr) {
    asm volatile("ldmatrix.sync.aligned.m8n8.x4.shared.b16 {%0,%1,%2,%3}, [%4];"
                 : "=r"(r[0]), "=r"(r[1]), "=r"(r[2]), "=r"(r[3]) : "r"(addr));
}
__device__ __forceinline__ void mma_bf16(float c[4], const uint32_t a[4],
                                         uint32_t b0, uint32_t b1) {
    asm volatile(
        "mma.sync.aligned.m16n8k16.row.col.f32.bf16.bf16.f32 "
        "{%0,%1,%2,%3}, {%4,%5,%6,%7}, {%8,%9}, {%0,%1,%2,%3};"
        : "+f"(c[0]), "+f"(c[1]), "+f"(c[2]), "+f"(c[3])
        : "r"(a[0]), "r"(a[1]), "r"(a[2]), "r"(a[3]), "r"(b0), "r"(b1));
}
__device__ __forceinline__ u64 pk2(float lo, float hi) {
    u64 r;
    asm("mov.b64 %0, {%1, %2};" : "=l"(r) : "f"(lo), "f"(hi));
    return r;
}
__device__ __forceinline__ void upk2(u64 v, float& lo, float& hi) {
    asm("mov.b64 {%0, %1}, %2;" : "=f"(lo), "=f"(hi) : "l"(v));
}
__device__ __forceinline__ void fma2(u64& d, u64 a, u64 b) {
    asm("fma.rn.f32x2 %0, %1, %2, %0;" : "+l"(d) : "l"(a), "l"(b));
}
__device__ __forceinline__ uint32_t mono_f(float f) {
    uint32_t u = __float_as_uint(f);
    return (u & 0x80000000u) ? ~u : (u | 0x80000000u);
}
__device__ __forceinline__ float unmono_f(uint32_t m) {
    uint32_t u = (m & 0x80000000u) ? (m ^ 0x80000000u) : ~m;
    return __uint_as_float(u);
}
__device__ __forceinline__ uint32_t bfpack(float a, float b) {
    uint32_t r;
    asm("cvt.rn.bf16x2.f32 %0, %2, %1;" : "=r"(r) : "f"(a), "f"(b));
    return r;   // low half = a, high half = b
}

// ============================================================================
// Projection (merged Q/K via blockIdx.z): O = x @ W^T + b -> fp32 + bf16.
// ============================================================================
#define BM 128
#define BN 128
#define BK 16
#define TM 8
#define TN 8

__global__ __launch_bounds__(256, 2) void proj_kernel(
    const float* __restrict__ A,
    const float* __restrict__ Wq, const float* __restrict__ bq,
    const float* __restrict__ Wk, const float* __restrict__ bk,
    float* __restrict__ Qf, __nv_bfloat16* __restrict__ Qh,
    float* __restrict__ Kf, __nv_bfloat16* __restrict__ Kh)
{
    const float* B  = blockIdx.z ? Wk : Wq;
    const float* bias = blockIdx.z ? bk : bq;
    float* Of = blockIdx.z ? Kf : Qf;
    __nv_bfloat16* Oh = blockIdx.z ? Kh : Qh;

    const int Kd = HID;
    const int tid = threadIdx.x;
    const int tx  = tid & 15;
    const int ty  = tid >> 4;
    const long bm = (long)blockIdx.y * BM;
    const long bn = (long)blockIdx.x * BN;

    __shared__ float As[2][BK][BM];
    __shared__ float Bs[2][BK][BN];

    u64 acc[TM][TN/2];
#pragma unroll
    for (int i = 0; i < TM; i++)
#pragma unroll
        for (int j = 0; j < TN/2; j++) acc[i][j] = 0ULL;

    const int lr = tid >> 1;
    const int lc = (tid & 1) * 8;
    const float* Abase = A + (bm + lr) * Kd + lc;
    const float* Bbase = B + (bn + lr) * Kd + lc;

    float4 ra0, ra1, rb0, rb1;
    ra0 = *(const float4*)(Abase);
    ra1 = *(const float4*)(Abase + 4);
    rb0 = *(const float4*)(Bbase);
    rb1 = *(const float4*)(Bbase + 4);
    {
        As[0][lc+0][lr]=ra0.x; As[0][lc+1][lr]=ra0.y; As[0][lc+2][lr]=ra0.z; As[0][lc+3][lr]=ra0.w;
        As[0][lc+4][lr]=ra1.x; As[0][lc+5][lr]=ra1.y; As[0][lc+6][lr]=ra1.z; As[0][lc+7][lr]=ra1.w;
        Bs[0][lc+0][lr]=rb0.x; Bs[0][lc+1][lr]=rb0.y; Bs[0][lc+2][lr]=rb0.z; Bs[0][lc+3][lr]=rb0.w;
        Bs[0][lc+4][lr]=rb1.x; Bs[0][lc+5][lr]=rb1.y; Bs[0][lc+6][lr]=rb1.z; Bs[0][lc+7][lr]=rb1.w;
    }
    __syncthreads();

    const int KT = Kd / BK;
    for (int kt = 0; kt < KT; ++kt) {
        const int buf = kt & 1;
        if (kt + 1 < KT) {
            const float* Ap = Abase + (kt + 1) * BK;
            const float* Bp = Bbase + (kt + 1) * BK;
            ra0 = *(const float4*)(Ap);  ra1 = *(const float4*)(Ap + 4);
            rb0 = *(const float4*)(Bp);  rb1 = *(const float4*)(Bp + 4);
        }
#pragma unroll
        for (int kk = 0; kk < BK; kk++) {
            float4 a0 = *(const float4*)&As[buf][kk][ty * TM];
            float4 a1 = *(const float4*)&As[buf][kk][ty * TM + 4];
            ulonglong2 b0 = *(const ulonglong2*)&Bs[buf][kk][tx * TN];
            ulonglong2 b1 = *(const ulonglong2*)&Bs[buf][kk][tx * TN + 4];
            u64 ad[TM] = {
                pk2(a0.x,a0.x), pk2(a0.y,a0.y), pk2(a0.z,a0.z), pk2(a0.w,a0.w),
                pk2(a1.x,a1.x), pk2(a1.y,a1.y), pk2(a1.z,a1.z), pk2(a1.w,a1.w)
            };
            u64 bd[4] = { b0.x, b0.y, b1.x, b1.y };
#pragma unroll
            for (int i = 0; i < TM; i++) {
                fma2(acc[i][0], ad[i], bd[0]);
                fma2(acc[i][1], ad[i], bd[1]);
                fma2(acc[i][2], ad[i], bd[2]);
                fma2(acc[i][3], ad[i], bd[3]);
            }
        }
        if (kt + 1 < KT) {
            const int nb = buf ^ 1;
            As[nb][lc+0][lr]=ra0.x; As[nb][lc+1][lr]=ra0.y; As[nb][lc+2][lr]=ra0.z; As[nb][lc+3][lr]=ra0.w;
            As[nb][lc+4][lr]=ra1.x; As[nb][lc+5][lr]=ra1.y; As[nb][lc+6][lr]=ra1.z; As[nb][lc+7][lr]=ra1.w;
            Bs[nb][lc+0][lr]=rb0.x; Bs[nb][lc+1][lr]=rb0.y; Bs[nb][lc+2][lr]=rb0.z; Bs[nb][lc+3][lr]=rb0.w;
            Bs[nb][lc+4][lr]=rb1.x; Bs[nb][lc+5][lr]=rb1.y; Bs[nb][lc+6][lr]=rb1.z; Bs[nb][lc+7][lr]=rb1.w;
        }
        __syncthreads();
    }

#pragma unroll
    for (int i = 0; i < TM; i++) {
        const long rrow = bm + ty * TM + i;
        const long cb = bn + tx * TN;
        float o[8];
        upk2(acc[i][0], o[0], o[1]);
        upk2(acc[i][1], o[2], o[3]);
        upk2(acc[i][2], o[4], o[5]);
        upk2(acc[i][3], o[6], o[7]);
        const float* bp = bias + cb;
#pragma unroll
        for (int j = 0; j < 8; j++) {
            float v = o[j] + bp[j];
            o[j] = v;
            Oh[rrow * HID + cb + j] = __float2bfloat16(v);
        }
        *(float4*)(Of + rrow * HID + cb)     = make_float4(o[0], o[1], o[2], o[3]);
        *(float4*)(Of + rrow * HID + cb + 4) = make_float4(o[4], o[5], o[6], o[7]);
    }
}

// ============================================================================
// Scores GEMM via mma.sync (bf16, single pass): S = Qh Kh^T / 16
// 3-stage cp.async pipeline; stores S as bf16.
// ============================================================================
#define SPITCH 40
#define SC_STG  10240                 // one stage of one matrix (128*40*2)
#define SC_SMEM (6 * SC_STG)          // 61440

__global__ __launch_bounds__(256) void scores_kernel()
{
    extern __shared__ __align__(16) char smem[];

    const int tid = threadIdx.x;
    const int wid = tid >> 5, l = tid & 31;
    const int wm = wid & 1;
    const int wn = wid >> 1;
    const long b  = blockIdx.z;
    const long bm = (long)blockIdx.y * 128;
    const long bn = (long)blockIdx.x * 128;

    const uint32_t sAu = smem_u32(smem);
    const uint32_t sBu = sAu + 3 * SC_STG;

    float cacc[4][4][4];
#pragma unroll
    for (int mi = 0; mi < 4; mi++)
#pragma unroll
        for (int ni = 0; ni < 4; ni++)
#pragma unroll
            for (int e = 0; e < 4; e++) cacc[mi][ni][e] = 0.f;

    auto fill = [&](int stage, int c) {
        const int kb = c * 64;   // 32 bf16 per chunk
        const char* Ag = (const char*)(d_Qh + (b * NN + bm) * HID) + kb;
        const char* Bg = (const char*)(d_Kh + (b * NN + bn) * HID) + kb;
        const uint32_t da = sAu + stage * SC_STG;
        const uint32_t db = sBu + stage * SC_STG;
#pragma unroll
        for (int i = 0; i < 2; i++) {
            const int idx = tid + i * 256;
            const int row = idx >> 2, ch = idx & 3;
            cp16(da + row * (SPITCH * 2) + ch * 16, Ag + (size_t)row * (HID * 2) + ch * 16);
            cp16(db + row * (SPITCH * 2) + ch * 16, Bg + (size_t)row * (HID * 2) + ch * 16);
        }
    };

    fill(0, 0);
    asm volatile("cp.async.commit_group;" ::: "memory");
    fill(1, 1);
    asm volatile("cp.async.commit_group;" ::: "memory");

    const int rA = ((l >> 3) & 1) * 8 + (l & 7);
    const int cA = (l >> 4) * 16;
    const int rB = (l >> 4) * 8 + (l & 7);
    const int cB = ((l >> 3) & 1) * 16;

    for (int c = 0; c < 8; c++) {
        const int s = c % 3;
        if (c < 7) asm volatile("cp.async.wait_group 1;" ::: "memory");
        else       asm volatile("cp.async.wait_group 0;" ::: "memory");
        __syncthreads();

        const uint32_t ab = sAu + s * SC_STG;
        const uint32_t bb = sBu + s * SC_STG;

        uint32_t af[2][4][4];
        uint32_t bf[2][2][4];
#pragma unroll
        for (int kk = 0; kk < 2; kk++) {
#pragma unroll
            for (int mi = 0; mi < 4; mi++)
                ldsm4(af[kk][mi],
                      ab + (uint32_t)(wm * 64 + mi * 16 + rA) * (SPITCH * 2) + kk * 32 + cA);
#pragma unroll
            for (int bi = 0; bi < 2; bi++)
                ldsm4(bf[kk][bi],
                      bb + (uint32_t)(wn * 32 + bi * 16 + rB) * (SPITCH * 2) + kk * 32 + cB);
        }

        if (c + 2 < 8) {
            fill((c + 2) % 3, c + 2);
            asm volatile("cp.async.commit_group;" ::: "memory");
        }

#pragma unroll
        for (int kk = 0; kk < 2; kk++)
#pragma unroll
            for (int mi = 0; mi < 4; mi++)
#pragma unroll
                for (int ni = 0; ni < 4; ni++) {
                    const int bi = ni >> 1, p = ni & 1;
                    mma_bf16(cacc[mi][ni], af[kk][mi],
                             bf[kk][bi][p * 2], bf[kk][bi][p * 2 + 1]);
                }
    }

    const int g = l >> 2, tg = l & 3;
#pragma unroll
    for (int mi = 0; mi < 4; mi++) {
        const long r0 = bm + wm * 64 + mi * 16 + g;
        __nv_bfloat16* S0 = d_Sb + ((size_t)(b * NN + r0)) * NN + bn + wn * 32;
        __nv_bfloat16* S1 = S0 + 8 * NN;
#pragma unroll
        for (int ni = 0; ni < 4; ni++) {
            const int co = ni * 8 + tg * 2;
            const uint32_t p0 = bfpack(cacc[mi][ni][0] * 0.0625f, cacc[mi][ni][1] * 0.0625f);
            const uint32_t p1 = bfpack(cacc[mi][ni][2] * 0.0625f, cacc[mi][ni][3] * 0.0625f);
            __stcs((uint32_t*)(S0 + co), p0);
            __stcs((uint32_t*)(S1 + co), p1);
        }
    }
}

// ============================================================================
// rowtopk v7 (bf16 input): threshold prefilter (T = min of warp maxes =>
// provable superset of block top-16), 512-entry buffer, 2-stage tournament.
// ============================================================================
#define CSW(x, y) do { u64 _a = (x), _b = (y); \
    (x) = _a > _b ? _a : _b; (y) = _a > _b ? _b : _a; } while (0)

__global__ __launch_bounds__(512) void rowtopk_kernel()
{
    const int row = blockIdx.x;
    const int tid = threadIdx.x, lid = tid & 31, wid = tid >> 5;   // 16 warps
    const uint4* S16 = (const uint4*)(d_Sb + (size_t)row * NN);

    __shared__ uint32_t wred[16];
    __shared__ float    wzs[16];
    __shared__ uint32_t bc[2];      // [0]=mono(block max), [1]=mono(T)
    __shared__ int      cnt;
    __shared__ u64      buf[512];
    __shared__ u64      sec[64];

    if (tid == 0) cnt = 0;

    const uint4 q = __ldcs(&S16[tid]);     // 8 bf16: elems 8*tid .. 8*tid+7
    float v[8];
    {
        const uint32_t w[4] = { q.x, q.y, q.z, q.w };
#pragma unroll
        for (int p = 0; p < 4; p++) {
            const __nv_bfloat162 h2 = *(const __nv_bfloat162*)&w[p];
            v[2*p]   = __bfloat162float(__low2bfloat16(h2));
            v[2*p+1] = __bfloat162float(__high2bfloat16(h2));
        }
    }

    float tmax = v[0];
#pragma unroll
    for (int i = 1; i < 8; i++) tmax = fmaxf(tmax, v[i]);
    const uint32_t wm = __reduce_max_sync(0xFFFFFFFFu, mono_f(tmax));
    if (lid == 0) wred[wid] = wm;
    __syncthreads();

    if (wid == 0) {
        const uint32_t tlo = (lid < 16) ? wred[lid] : 0xFFFFFFFFu;
        const uint32_t tmin = __reduce_min_sync(0xFFFFFFFFu, tlo);
        const uint32_t thi = (lid < 16) ? wred[lid] : 0u;
        const uint32_t tmx = __reduce_max_sync(0xFFFFFFFFu, thi);
        if (lid == 0) { bc[0] = tmx; bc[1] = tmin; }
    }
    __syncthreads();
    const float m = unmono_f(bc[0]);
    const float T = unmono_f(bc[1]);

    // Z with fixed block max
    float z = 0.f;
#pragma unroll
    for (int i = 0; i < 8; i++) z += __expf(v[i] - m);
#pragma unroll
    for (int o = 16; o; o >>= 1) z += __shfl_xor_sync(0xFFFFFFFFu, z, o);
    if (lid == 0) wzs[wid] = z;

    // filter: keep v >= T (deterministic superset of block top-16)
#pragma unroll
    for (int i = 0; i < 8; i++) {
        if (v[i] >= T) {
            const int gi = tid * 8 + i;
            const int p = atomicAdd(&cnt, 1);
            if (p < 512)
                buf[p] = ((u64)mono_f(v[i]) << 32) | (unsigned)(4095 - gi);
        }
    }
    __syncthreads();
    const int n = min(cnt, 512);

    // ---- Stage A: warps 0-3 reduce buf[wid*128 .. +128) to top-16 ----
    if (wid < 4) {
        u64 a[4];
#pragma unroll
        for (int j = 0; j < 4; j++) {
            const int p = wid * 128 + lid + 32 * j;
            a[j] = (p < n) ? buf[p] : 0ULL;
        }
        CSW(a[0], a[1]); CSW(a[2], a[3]); CSW(a[0], a[2]); CSW(a[1], a[3]); CSW(a[1], a[2]);

        int h = 0;
        u64 cur = a[0];
        for (int r = 0; r < 16; r++) {
            const uint32_t hi  = (uint32_t)(cur >> 32);
            const uint32_t win = __reduce_max_sync(0xFFFFFFFFu, hi);
            const uint32_t bal = __ballot_sync(0xFFFFFFFFu, hi == win);
            const int wl = __ffs(bal) - 1;
            if (lid == wl) {
                sec[wid * 16 + r] = cur;
                h++;
                cur = (h < 4) ? a[h] : 0ULL;
            }
        }
    }
    __syncthreads();

    // ---- Stage B: warp 0 reduces the 64 semifinalists to top-16 ----
    if (wid == 0) {
        u64 a[2] = { sec[lid * 2], sec[lid * 2 + 1] };
        CSW(a[0], a[1]);

        int h = 0;
        u64 cur = a[0];
        for (int r = 0; r < NCAND; r++) {
            const uint32_t hi  = (uint32_t)(cur >> 32);
            const uint32_t win = __reduce_max_sync(0xFFFFFFFFu, hi);
            const uint32_t bal = __ballot_sync(0xFFFFFFFFu, hi == win);
            const int wl = __ffs(bal) - 1;
            if (lid == wl) {
                d_C16[row * NCAND + r] = 4095 - (int)(cur & 0xFFFFFFFFu);
                h++;
                cur = (h < 2) ? a[h] : 0ULL;
            }
        }
        if (lid == 0) {
            float Z = 0.f;
#pragma unroll
            for (int w = 0; w < 16; w++) Z += wzs[w];
            d_Mv[row] = m;
            d_Zv[row] = Z;
        }
    }
}

// ============================================================================
// rescore v2: same R1-matched sequential fp32 fma chain (k ascending), but
// float4 K-row loads (64 x 16B per candidate instead of 256 x 4B scalar)
// -> 4x fewer L1 wavefronts. Bit-identical arithmetic.
// ============================================================================
__global__ __launch_bounds__(256) void rescore_kernel()
{
    __shared__ __align__(16) float sq[8][HID];
    const int wid = threadIdx.x >> 5, lane = threadIdx.x & 31;
    const int row = blockIdx.x * 8 + wid;
    const int b = row >> 12;

    for (int i = lane; i < HID / 4; i += 32)
        ((float4*)sq[wid])[i] = ((const float4*)(d_Qf + (size_t)row * HID))[i];
    __syncwarp();

    float s = 0.f; int j = 0;
    if (lane < NCAND) {
        j = d_C16[row * NCAND + lane];
        const float4* kr4 = (const float4*)(d_Kf + ((size_t)((b << 12) + j)) * HID);
        const float4* qr4 = (const float4*)sq[wid];
        float acc = 0.f;
#pragma unroll 8
        for (int kc = 0; kc < HID / 4; kc++) {
            const float4 kv = __ldg(&kr4[kc]);
            const float4 qv = qr4[kc];
            acc = fmaf(qv.x, kv.x, acc);
            acc = fmaf(qv.y, kv.y, acc);
            acc = fmaf(qv.z, kv.z, acc);
            acc = fmaf(qv.w, kv.w, acc);
        }
        s = acc * 0.0625f;
    }

    float scs[NCAND]; int ixs[NCAND];
#pragma unroll
    for (int c = 0; c < NCAND; c++) {
        scs[c] = __shfl_sync(0xFFFFFFFFu, s, c);
        ixs[c] = __shfl_sync(0xFFFFFFFFu, j, c);
    }

    if (lane == 0) {
        u64 key[NCAND];
#pragma unroll
        for (int c = 0; c < NCAND; c++)
            key[c] = ((u64)mono_f(scs[c]) << 32) | (unsigned)(4095 - ixs[c]);
        for (int i = 1; i < NCAND; i++) {
            u64 kv = key[i];
            int jj = i;
            while (jj > 0 && key[jj-1] < kv) { key[jj] = key[jj-1]; jj--; }
            key[jj] = kv;
        }
        const float m = d_Mv[row], z = d_Zv[row];
        float ev[KNN]; int oi[KNN]; float E8 = 0.f;
#pragma unroll
        for (int k = 0; k < KNN; k++) {
            const uint32_t mv = (uint32_t)(key[k] >> 32);
            const uint32_t u = (mv & 0x80000000u) ? (mv ^ 0x80000000u) : ~mv;
            const float sv = __uint_as_float(u);
            oi[k] = 4095 - (int)(key[k] & 0xFFFFFFFFu);
            ev[k] = __expf(sv - m);
            E8 += ev[k];
        }
        const float inv = 1.0f / (E8 + 1e-6f * z);
#pragma unroll
        for (int k = 0; k < KNN; k++) {
            d_TopV[row * KNN + k] = ev[k] * inv;
            d_TopI[row * KNN + k] = oi[k];
        }
    }
}

// ============================================================================
// Output: zero then symmetric sparse scatter (0.5*(A + A^T))
// ============================================================================
__global__ void zero_kernel(float* __restrict__ out)
{
    const size_t i = (size_t)blockIdx.x * blockDim.x + threadIdx.x;
    ((float4*)out)[i] = make_float4(0.f, 0.f, 0.f, 0.f);
}

__global__ void scatter_kernel(float* __restrict__ out)
{
    const int t = blockIdx.x * blockDim.x + threadIdx.x;
    if (t >= ROWS * KNN) return;
    const int row = t / KNN;
    const int b = row >> 12;
    const int i = row & (NN - 1);
    const int j = d_TopI[t];
    const float v = 0.5f * d_TopV[t];
    float* base = out + (size_t)b * NN * NN;
    atomicAdd(base + (size_t)i * NN + j, v);
    atomicAdd(base + (size_t)j * NN + i, v);
}

// ============================================================================
extern "C" void kernel_launch(void* const* d_in, const int* in_sizes, int n_in,
                              void* d_out, int out_size)
{
    const float* x  = (const float*)d_in[0];
    const float* Wq = (const float*)d_in[1];
    const float* bq = (const float*)d_in[2];
    const float* Wk = (const float*)d_in[3];
    const float* bk = (const float*)d_in[4];
    float* out = (float*)d_out;

    void *pqh, *pkh, *pqf, *pkf;
    cudaGetSymbolAddress(&pqh, d_Qh);
    cudaGetSymbolAddress(&pkh, d_Kh);
    cudaGetSymbolAddress(&pqf, d_Qf);
    cudaGetSymbolAddress(&pkf, d_Kf);

    cudaFuncSetAttribute(scores_kernel,
                         cudaFuncAttributeMaxDynamicSharedMemorySize, SC_SMEM);

    // 1) projections (Q and K in one launch via blockIdx.z)
    dim3 gProj(HID / BN, ROWS / BM, 2);
    proj_kernel<<<gProj, 256>>>(x, Wq, bq, Wk, bk,
                                (float*)pqf, (__nv_bfloat16*)pqh,
                                (float*)pkf, (__nv_bfloat16*)pkh);

    // 2) scores via mma.sync bf16 (single pass, 3-stage pipeline, bf16 out)
    dim3 gS(NN / 128, NN / 128, BATCH);
    scores_kernel<<<gS, 256, SC_SMEM>>>();

    // 3) (m, Z) + top-16 candidates via threshold prefilter + 2-stage tournament
    rowtopk_kernel<<<ROWS, 512>>>();

    // 4) fp32 sequential-k rescoring (float4 loads) + exact top-8 pick
    rescore_kernel<<<ROWS / 8, 256>>>();

    // 5) zero output, 6) symmetric sparse scatter
    zero_kernel<<<((size_t)BATCH * NN * NN / 4) / 256, 256>>>(out);
    scatter_kernel<<<(ROWS * KNN + 255) / 256, 256>>>(out);
}